// round 10
// baseline (speedup 1.0000x reference)
#include <cuda_runtime.h>
#include <cuda_fp16.h>
#include <math.h>
#include <stdint.h>

#define BB 4
#define NN 2048
#define MM 2048
#define HH 8
#define DHD 64
#define INNERD 512
#define MP 2049
#define MPAD 2176          // 34 * 64
#define KT 64
#define QT 128
#define NTILES (MPAD / KT) // 34
#define NEG_MAX 3.402823466e38f

// Scratch (device globals; no allocation allowed)
__device__ __half g_Qh[(size_t)BB*HH*NN*DHD];    // [b,h,n,d]  tanh(q)*scale
__device__ __half g_Kh[(size_t)BB*HH*MPAD*DHD];  // [b,h,j,d]  tanh(k), j=0 null
__device__ __half g_Vh[(size_t)BB*HH*MPAD*DHD];  // [b,h,j,d]
__device__ __half g_Oh[(size_t)BB*NN*INNERD];    // [b,n,h*d]
__device__ float  g_kbias[BB*MPAD];              // 0 attend / -FLT_MAX masked / -INF pad
__device__ float  g_kbias2[BB*MPAD];             // 0 non-pad / -INF pad (masked-query rows)
__device__ __half g_xh[(size_t)BB*NN*512];
__device__ __half g_ch[(size_t)BB*MM*512];
__device__ __half g_wqh[512*512];
__device__ __half g_wkvh[512*1024];
__device__ __half g_woh[512*512];

__device__ __forceinline__ uint32_t smem_u32(const void* p) {
    return (uint32_t)__cvta_generic_to_shared(p);
}
__device__ __forceinline__ void ldsm4(uint32_t* r, uint32_t a) {
    asm volatile("ldmatrix.sync.aligned.m8n8.x4.shared.b16 {%0,%1,%2,%3}, [%4];"
        : "=r"(r[0]), "=r"(r[1]), "=r"(r[2]), "=r"(r[3]) : "r"(a));
}
__device__ __forceinline__ void ldsm4t(uint32_t* r, uint32_t a) {
    asm volatile("ldmatrix.sync.aligned.m8n8.x4.trans.shared.b16 {%0,%1,%2,%3}, [%4];"
        : "=r"(r[0]), "=r"(r[1]), "=r"(r[2]), "=r"(r[3]) : "r"(a));
}
__device__ __forceinline__ void mma16(float* d, const uint32_t* a, uint32_t b0, uint32_t b1) {
    asm volatile(
        "mma.sync.aligned.m16n8k16.row.col.f32.f16.f16.f32 "
        "{%0,%1,%2,%3}, {%4,%5,%6,%7}, {%8,%9}, {%0,%1,%2,%3};"
        : "+f"(d[0]), "+f"(d[1]), "+f"(d[2]), "+f"(d[3])
        : "r"(a[0]), "r"(a[1]), "r"(a[2]), "r"(a[3]), "r"(b0), "r"(b1));
}
__device__ __forceinline__ void cpa16(void* dst, const void* src) {
    uint32_t d = smem_u32(dst);
    asm volatile("cp.async.cg.shared.global [%0], [%1], 16;\n" :: "r"(d), "l"(src));
}
#define CP_COMMIT() asm volatile("cp.async.commit_group;\n" ::: "memory")
#define CP_WAIT(n)  asm volatile("cp.async.wait_group %0;\n" :: "n"(n) : "memory")

// ---------------------------------------------------------------------------
// Fused prep: fp32->fp16 rounding of all inputs + kbias tables + null/pad KV
// ---------------------------------------------------------------------------
#define N4_X   (BB*NN*512/4)
#define N4_C   (BB*MM*512/4)
#define N4_WQ  (512*512/4)
#define N4_WKV (512*1024/4)
#define N4_WO  (512*512/4)
#define N4_TOT (N4_X + N4_C + N4_WQ + N4_WKV + N4_WO)
#define NB_ROUND ((N4_TOT + 255) / 256)              // 9216
#define NB_BIAS  ((BB * MPAD + 255) / 256)           // 34
#define NB_KV    (BB * HH)                           // 32

__global__ void prep_all_kernel(const float* __restrict__ x, const float* __restrict__ ctx,
                                const float* __restrict__ wq, const float* __restrict__ wkv,
                                const float* __restrict__ wo,
                                const unsigned int* __restrict__ cmask,
                                const float* __restrict__ null_key,
                                const float* __restrict__ null_value) {
    int blk = blockIdx.x;
    if (blk < NB_ROUND) {
        int i = blk * 256 + threadIdx.x;
        if (i >= N4_TOT) return;
        const float* src; __half* dst; int off;
        if (i < N4_X)                      { src = x;   dst = g_xh;   off = i; }
        else if (i < N4_X + N4_C)          { src = ctx; dst = g_ch;   off = i - N4_X; }
        else if (i < N4_X + N4_C + N4_WQ)  { src = wq;  dst = g_wqh;  off = i - N4_X - N4_C; }
        else if (i < N4_X + N4_C + N4_WQ + N4_WKV)
                                           { src = wkv; dst = g_wkvh; off = i - N4_X - N4_C - N4_WQ; }
        else                               { src = wo;  dst = g_woh;  off = i - N4_X - N4_C - N4_WQ - N4_WKV; }
        float4 v = ((const float4*)src)[off];
        __half2* d2 = (__half2*)dst;
        d2[2 * off]     = __floats2half2_rn(v.x, v.y);
        d2[2 * off + 1] = __floats2half2_rn(v.z, v.w);
    } else if (blk < NB_ROUND + NB_BIAS) {
        int t = (blk - NB_ROUND) * 256 + threadIdx.x;
        if (t >= BB * MPAD) return;
        int b = t / MPAD, j = t % MPAD;
        float v, v2;
        if (j == 0)        { v = 0.f; v2 = 0.f; }
        else if (j <= MM)  { v = (cmask[b * MM + (j - 1)] != 0u) ? 0.f : -NEG_MAX; v2 = 0.f; }
        else               { v = -INFINITY; v2 = -INFINITY; }
        g_kbias[t] = v;
        g_kbias2[t] = v2;
    } else {
        int bh = blk - NB_ROUND - NB_BIAS;
        __half* Kb = g_Kh + (size_t)bh * MPAD * DHD;
        __half* Vb = g_Vh + (size_t)bh * MPAD * DHD;
        int t = threadIdx.x;
        if (t < DHD) {
            Kb[t] = __float2half_rn(tanhf(null_key[t]));
            Vb[t] = __float2half_rn(null_value[t]);
        }
        for (int idx = t; idx < DHD * (MPAD - MP); idx += 256) {
            int d = idx & 63, jr = idx >> 6;
            Kb[(size_t)(MP + jr) * DHD + d] = __float2half_rn(0.f);
            Vb[(size_t)(MP + jr) * DHD + d] = __float2half_rn(0.f);
        }
    }
}

// ---------------------------------------------------------------------------
// fp16 mma GEMM: k-chunk 64 (8 iters), MLP=8 cp.async, 2 CTA/SM.
// mode 0: Q proj; 1: KV proj; 2: O proj; 3: fused Q+KV dispatch
// ---------------------------------------------------------------------------
__global__ __launch_bounds__(256, 2) void gemm_mma_h(
    const __half* __restrict__ A, const __half* __restrict__ W,
    const float* __restrict__ bias, float* __restrict__ out,
    int Ncols, int mode)
{
    __shared__ __align__(16) __half As[2][128][72];   // [m][k64+pad]
    __shared__ __align__(16) __half Bs[2][64][136];   // [k64][n128+pad]

    int t = threadIdx.x, lane = t & 31, w = t >> 5;
    int wm = w >> 2, wn = w & 3;
    int g = lane >> 2, cl = lane & 3;
    int row0 = blockIdx.y * 128;
    int col0;
    if (mode == 3) {
        if (blockIdx.x < 4) { A = g_xh; W = g_wqh;  Ncols = 512;  mode = 0; col0 = blockIdx.x * 128; }
        else                { A = g_ch; W = g_wkvh; Ncols = 1024; mode = 1; col0 = (blockIdx.x - 4) * 128; }
    } else {
        col0 = blockIdx.x * 128;
    }

    // A: 2 threads/row, 4 x 16B chunks each. B: 4 threads/row, 4 x 16B chunks.
    int ar = t >> 1, ac = (t & 1) * 32;
    int br = t >> 2, bc = (t & 3) * 32;

    float acc[4][4][4] = {};

    #pragma unroll
    for (int c = 0; c < 4; c++) {
        cpa16(&As[0][ar][ac + c * 8], A + (size_t)(row0 + ar) * 512 + ac + c * 8);
        cpa16(&Bs[0][br][bc + c * 8], W + (size_t)br * Ncols + col0 + bc + c * 8);
    }
    CP_COMMIT();

    int a_lr = lane & 15, a_lc = (lane >> 4) * 8;
    int b_lr = (lane & 7) + 8 * ((lane >> 3) & 1), b_lc = 8 * (lane >> 4);

    int p = 0;
    for (int kt = 0; kt < 8; kt++) {
        if (kt < 7) {
            int k0 = (kt + 1) * 64;
            #pragma unroll
            for (int c = 0; c < 4; c++) {
                cpa16(&As[1 - p][ar][ac + c * 8], A + (size_t)(row0 + ar) * 512 + k0 + ac + c * 8);
                cpa16(&Bs[1 - p][br][bc + c * 8], W + (size_t)(k0 + br) * Ncols + col0 + bc + c * 8);
            }
            CP_COMMIT(); CP_WAIT(1);
        } else {
            CP_WAIT(0);
        }
        __syncthreads();

        #pragma unroll
        for (int kc = 0; kc < 4; kc++) {
            uint32_t af[4][4];
            #pragma unroll
            for (int mi = 0; mi < 4; mi++)
                ldsm4(af[mi], smem_u32(&As[p][wm * 64 + mi * 16 + a_lr][kc * 16 + a_lc]));
            #pragma unroll
            for (int np = 0; np < 2; np++) {
                uint32_t bf[4];
                ldsm4t(bf, smem_u32(&Bs[p][kc * 16 + b_lr][wn * 32 + np * 16 + b_lc]));
                #pragma unroll
                for (int mi = 0; mi < 4; mi++) {
                    mma16(acc[mi][np * 2],     af[mi], bf[0], bf[1]);
                    mma16(acc[mi][np * 2 + 1], af[mi], bf[2], bf[3]);
                }
            }
        }
        __syncthreads();
        p ^= 1;
    }

    int bidx = row0 >> 11;
    #pragma unroll
    for (int mi = 0; mi < 4; mi++) {
        int r0 = row0 + wm * 64 + mi * 16 + g;
        int n0r = r0 & 2047;
        #pragma unroll
        for (int ni = 0; ni < 4; ni++) {
            int c = col0 + wn * 32 + ni * 8 + 2 * cl;
            float v0 = acc[mi][ni][0], v1 = acc[mi][ni][1];
            float v2 = acc[mi][ni][2], v3 = acc[mi][ni][3];
            if (mode == 0) {
                int hh = c >> 6, d = c & 63;
                *(__half2*)&g_Qh[(((size_t)bidx * HH + hh) * NN + n0r) * DHD + d] =
                    __floats2half2_rn(tanhf(v0) * 0.125f, tanhf(v1) * 0.125f);
                *(__half2*)&g_Qh[(((size_t)bidx * HH + hh) * NN + n0r + 8) * DHD + d] =
                    __floats2half2_rn(tanhf(v2) * 0.125f, tanhf(v3) * 0.125f);
            } else if (mode == 1) {
                if (c < INNERD) {
                    int hh = c >> 6, d = c & 63;
                    *(__half2*)&g_Kh[(((size_t)bidx * HH + hh) * MPAD + n0r + 1) * DHD + d] =
                        __floats2half2_rn(tanhf(v0), tanhf(v1));
                    *(__half2*)&g_Kh[(((size_t)bidx * HH + hh) * MPAD + n0r + 9) * DHD + d] =
                        __floats2half2_rn(tanhf(v2), tanhf(v3));
                } else {
                    int c2 = c - INNERD;
                    int hh = c2 >> 6, d = c2 & 63;
                    *(__half2*)&g_Vh[(((size_t)bidx * HH + hh) * MPAD + n0r + 1) * DHD + d] =
                        __floats2half2_rn(v0, v1);
                    *(__half2*)&g_Vh[(((size_t)bidx * HH + hh) * MPAD + n0r + 9) * DHD + d] =
                        __floats2half2_rn(v2, v3);
                }
            } else {
                float b0v = bias[c], b1v = bias[c + 1];
                *(float2*)&out[(size_t)r0 * 512 + c]       = make_float2(v0 + b0v, v1 + b1v);
                *(float2*)&out[(size_t)(r0 + 8) * 512 + c] = make_float2(v2 + b0v, v3 + b1v);
            }
        }
    }
}

// ---------------------------------------------------------------------------
// Flash attention: fp16 mma, register P, K+V+bias double-buffered,
// ONE __syncthreads per key tile. (unchanged from R9)
// ---------------------------------------------------------------------------
struct __align__(16) AttnSmemH {
    __half Qs[128][72];       // [q][d]
    __half Kt[2][64][72];     // [j][d]
    __half Vs[2][64][72];     // [j][d]
    float kb[2][64];
    float kbq[2][64];
};

__device__ __forceinline__ void cp_kv_tile(AttnSmemH& s, int buf, const __half* Kb,
                                           const __half* Vb, int j0, int t) {
    #pragma unroll
    for (int i = 0; i < 2; i++) {
        int e = t + i * 256;
        int r = e >> 3, c8 = (e & 7) * 8;
        cpa16(&s.Kt[buf][r][c8], Kb + (size_t)(j0 + r) * DHD + c8);
        cpa16(&s.Vs[buf][r][c8], Vb + (size_t)(j0 + r) * DHD + c8);
    }
}

__global__ __launch_bounds__(256, 2) void attn_kernel(const unsigned int* __restrict__ qmask) {
    extern __shared__ char smem_raw[];
    AttnSmemH& s = *reinterpret_cast<AttnSmemH*>(smem_raw);

    int t = threadIdx.x, lane = t & 31, w = t >> 5;
    int n0 = blockIdx.x * QT;
    int h = blockIdx.y, b = blockIdx.z;
    int bh = b * HH + h;

    const __half* Qb = g_Qh + (size_t)bh * NN * DHD;
    const __half* Kb = g_Kh + (size_t)bh * MPAD * DHD;
    const __half* Vb = g_Vh + (size_t)bh * MPAD * DHD;
    const float* kb_base  = g_kbias  + b * MPAD;
    const float* kbq_base = g_kbias2 + b * MPAD;

    #pragma unroll
    for (int i = 0; i < 4; i++) {
        int e = t + i * 256;
        int q = e >> 3, c8 = (e & 7) * 8;
        *(uint4*)&s.Qs[q][c8] = *(const uint4*)&Qb[(size_t)(n0 + q) * DHD + c8];
    }
    cp_kv_tile(s, 0, Kb, Vb, 0, t);
    CP_COMMIT();
    if (t < 64) {
        s.kb[0][t]  = kb_base[t];
        s.kbq[0][t] = kbq_base[t];
    }
    CP_WAIT(0);
    __syncthreads();

    int g = lane >> 2, cl = lane & 3;
    int row_lo = w * 16 + g;
    int a_lr = lane & 15, a_lc = (lane >> 4) * 8;

    uint32_t aq[4][4];
    #pragma unroll
    for (int ko = 0; ko < 4; ko++)
        ldsm4(aq[ko], smem_u32(&s.Qs[w * 16 + a_lr][ko * 16 + a_lc]));

    int qml = (qmask[b * NN + n0 + row_lo]     != 0u) ? 1 : 0;
    int qmh = (qmask[b * NN + n0 + row_lo + 8] != 0u) ? 1 : 0;

    float m_lo = -NEG_MAX, m_hi = -NEG_MAX, l_lo = 0.f, l_hi = 0.f;
    float oacc[8][4] = {};
    int p = 0;

    int k_lr = (lane & 7) + 8 * (lane >> 4);
    int k_lc = 8 * ((lane >> 3) & 1);
    int v_lr = (lane & 7) + 8 * ((lane >> 3) & 1);
    int v_lc = 8 * (lane >> 4);

    for (int kt = 0; kt < NTILES; kt++) {
        if (kt < NTILES - 1) {
            int j1 = (kt + 1) * KT;
            cp_kv_tile(s, 1 - p, Kb, Vb, j1, t);
            CP_COMMIT();
            if (t < 64) {
                s.kb[1 - p][t]  = kb_base[j1 + t];
                s.kbq[1 - p][t] = kbq_base[j1 + t];
            }
        }

        // ---- S = Q K^T from buffer p ----
        float sacc[8][4] = {};
        #pragma unroll
        for (int ko = 0; ko < 4; ko++) {
            #pragma unroll
            for (int ntp = 0; ntp < 4; ntp++) {
                uint32_t bf[4];
                ldsm4(bf, smem_u32(&s.Kt[p][ntp * 16 + k_lr][ko * 16 + k_lc]));
                mma16(sacc[ntp * 2],     aq[ko], bf[0], bf[1]);
                mma16(sacc[ntp * 2 + 1], aq[ko], bf[2], bf[3]);
            }
        }

        // ---- mask + online softmax ----
        float mx_lo = m_lo, mx_hi = m_hi;
        #pragma unroll
        for (int nt = 0; nt < 8; nt++) {
            int c = nt * 8 + 2 * cl;
            float kb0 = s.kb[p][c], kb1 = s.kb[p][c + 1];
            float kq0 = s.kbq[p][c], kq1 = s.kbq[p][c + 1];
            float x0 = qml ? sacc[nt][0] + kb0 : kq0;
            float x1 = qml ? sacc[nt][1] + kb1 : kq1;
            float x2 = qmh ? sacc[nt][2] + kb0 : kq0;
            float x3 = qmh ? sacc[nt][3] + kb1 : kq1;
            sacc[nt][0] = x0; sacc[nt][1] = x1; sacc[nt][2] = x2; sacc[nt][3] = x3;
            mx_lo = fmaxf(mx_lo, fmaxf(x0, x1));
            mx_hi = fmaxf(mx_hi, fmaxf(x2, x3));
        }
        mx_lo = fmaxf(mx_lo, __shfl_xor_sync(0xffffffffu, mx_lo, 1));
        mx_lo = fmaxf(mx_lo, __shfl_xor_sync(0xffffffffu, mx_lo, 2));
        mx_hi = fmaxf(mx_hi, __shfl_xor_sync(0xffffffffu, mx_hi, 1));
        mx_hi = fmaxf(mx_hi, __shfl_xor_sync(0xffffffffu, mx_hi, 2));

        float al_lo = __expf(m_lo - mx_lo); m_lo = mx_lo;
        float al_hi = __expf(m_hi - mx_hi); m_hi = mx_hi;

        uint32_t pf_lo[8], pf_hi[8];
        float sum_lo = 0.f, sum_hi = 0.f;
        #pragma unroll
        for (int nt = 0; nt < 8; nt++) {
            float p0 = __expf(sacc[nt][0] - mx_lo);
            float p1 = __expf(sacc[nt][1] - mx_lo);
            float p2 = __expf(sacc[nt][2] - mx_hi);
            float p3 = __expf(sacc[nt][3] - mx_hi);
            __half2 hlo = __floats2half2_rn(p0, p1);
            __half2 hhi = __floats2half2_rn(p2, p3);
            float2 flo = __half22float2(hlo), fhi = __half22float2(hhi);
            sum_lo += flo.x + flo.y;
            sum_hi += fhi.x + fhi.y;
            pf_lo[nt] = *(uint32_t*)&hlo;
            pf_hi[nt] = *(uint32_t*)&hhi;
        }
        sum_lo += __shfl_xor_sync(0xffffffffu, sum_lo, 1);
        sum_lo += __shfl_xor_sync(0xffffffffu, sum_lo, 2);
        sum_hi += __shfl_xor_sync(0xffffffffu, sum_hi, 1);
        sum_hi += __shfl_xor_sync(0xffffffffu, sum_hi, 2);
        l_lo = l_lo * al_lo + sum_lo;
        l_hi = l_hi * al_hi + sum_hi;

        // ---- rescale + O += P V from buffer p ----
        #pragma unroll
        for (int nt = 0; nt < 8; nt++) {
            oacc[nt][0] *= al_lo; oacc[nt][1] *= al_lo;
            oacc[nt][2] *= al_hi; oacc[nt][3] *= al_hi;
        }
        #pragma unroll
        for (int ko2 = 0; ko2 < 4; ko2++) {
            uint32_t pa[4] = { pf_lo[ko2 * 2], pf_hi[ko2 * 2],
                               pf_lo[ko2 * 2 + 1], pf_hi[ko2 * 2 + 1] };
            #pragma unroll
            for (int ntp = 0; ntp < 4; ntp++) {
                uint32_t bf[4];
                ldsm4t(bf, smem_u32(&s.Vs[p][ko2 * 16 + v_lr][ntp * 16 + v_lc]));
                mma16(oacc[ntp * 2],     pa, bf[0], bf[1]);
                mma16(oacc[ntp * 2 + 1], pa, bf[2], bf[3]);
            }
        }

        if (kt < NTILES - 1) {
            CP_WAIT(0);
            __syncthreads();
        }
        p ^= 1;
    }

    float li_lo = 1.f / l_lo, li_hi = 1.f / l_hi;
    #pragma unroll
    for (int nt = 0; nt < 8; nt++) {
        int c = nt * 8 + 2 * cl;
        size_t base_lo = ((size_t)b * NN + n0 + row_lo) * INNERD + h * DHD + c;
        size_t base_hi = ((size_t)b * NN + n0 + row_lo + 8) * INNERD + h * DHD + c;
        *(__half2*)&g_Oh[base_lo] = __floats2half2_rn(oacc[nt][0] * li_lo, oacc[nt][1] * li_lo);
        *(__half2*)&g_Oh[base_hi] = __floats2half2_rn(oacc[nt][2] * li_hi, oacc[nt][3] * li_hi);
    }
}

// ---------------------------------------------------------------------------
extern "C" void kernel_launch(void* const* d_in, const int* in_sizes, int n_in,
                              void* d_out, int out_size) {
    const float* x            = (const float*)d_in[0];
    const float* ctx          = (const float*)d_in[1];
    const unsigned int* mask  = (const unsigned int*)d_in[2];
    const unsigned int* cmask = (const unsigned int*)d_in[3];
    const float* Wq  = (const float*)d_in[4];
    const float* Wkv = (const float*)d_in[5];
    const float* Wo  = (const float*)d_in[6];
    const float* bo  = (const float*)d_in[7];
    const float* nk  = (const float*)d_in[8];
    const float* nv  = (const float*)d_in[9];
    float* out = (float*)d_out;

    static int inited = 0;
    if (!inited) {
        cudaFuncSetAttribute(attn_kernel, cudaFuncAttributeMaxDynamicSharedMemorySize,
                             (int)sizeof(AttnSmemH));
        inited = 1;
    }

    __half *oh, *woh;
    cudaGetSymbolAddress((void**)&oh,  g_Oh);
    cudaGetSymbolAddress((void**)&woh, g_woh);

    // fused prep: rounding + bias tables + null/pad KV (all independent)
    prep_all_kernel<<<NB_ROUND + NB_BIAS + NB_KV, 256>>>(x, ctx, Wq, Wkv, Wo, cmask, nk, nv);

    // fused Q + KV projection (mode 3 dispatch)
    dim3 gqkv(12, 64);
    gemm_mma_h<<<gqkv, 256>>>(nullptr, nullptr, nullptr, nullptr, 0, 3);

    dim3 ga(NN / QT, HH, BB);                        // (16, 8, 4)
    attn_kernel<<<ga, 256, sizeof(AttnSmemH)>>>(mask);

    dim3 g2(512 / 128, (BB * NN) / 128);             // (4, 64)
    gemm_mma_h<<<g2, 256>>>(oh, woh, bo, out, 512, 2);
}

// round 11
// speedup vs baseline: 1.1792x; 1.1792x over previous
#include <cuda_runtime.h>
#include <cuda_fp16.h>
#include <math.h>
#include <stdint.h>

#define BB 4
#define NN 2048
#define MM 2048
#define HH 8
#define DHD 64
#define INNERD 512
#define MP 2049
#define MPAD 2176          // 34 * 64
#define KT 64
#define QT 128
#define NTILES (MPAD / KT) // 34
#define NEG_MAX 3.402823466e38f

// Scratch (device globals; no allocation allowed)
__device__ __half g_Qh[(size_t)BB*HH*NN*DHD];    // [b,h,n,d]  tanh(q)*scale
__device__ __half g_Kh[(size_t)BB*HH*MPAD*DHD];  // [b,h,j,d]  tanh(k), j=0 null
__device__ __half g_Vh[(size_t)BB*HH*MPAD*DHD];  // [b,h,j,d]
__device__ __half g_Oh[(size_t)BB*NN*INNERD];    // [b,n,h*d]
__device__ float  g_kbias[BB*MPAD];              // 0 attend / -FLT_MAX masked / -INF pad
__device__ float  g_kbias2[BB*MPAD];             // 0 non-pad / -INF pad (masked-query rows)
__device__ __half g_xh[(size_t)BB*NN*512];
__device__ __half g_ch[(size_t)BB*MM*512];
__device__ __half g_wqh[512*512];
__device__ __half g_wkvh[512*1024];
__device__ __half g_woh[512*512];

__device__ __forceinline__ uint32_t smem_u32(const void* p) {
    return (uint32_t)__cvta_generic_to_shared(p);
}
__device__ __forceinline__ void ldsm4(uint32_t* r, uint32_t a) {
    asm volatile("ldmatrix.sync.aligned.m8n8.x4.shared.b16 {%0,%1,%2,%3}, [%4];"
        : "=r"(r[0]), "=r"(r[1]), "=r"(r[2]), "=r"(r[3]) : "r"(a));
}
__device__ __forceinline__ void ldsm4t(uint32_t* r, uint32_t a) {
    asm volatile("ldmatrix.sync.aligned.m8n8.x4.trans.shared.b16 {%0,%1,%2,%3}, [%4];"
        : "=r"(r[0]), "=r"(r[1]), "=r"(r[2]), "=r"(r[3]) : "r"(a));
}
__device__ __forceinline__ void mma16(float* d, const uint32_t* a, uint32_t b0, uint32_t b1) {
    asm volatile(
        "mma.sync.aligned.m16n8k16.row.col.f32.f16.f16.f32 "
        "{%0,%1,%2,%3}, {%4,%5,%6,%7}, {%8,%9}, {%0,%1,%2,%3};"
        : "+f"(d[0]), "+f"(d[1]), "+f"(d[2]), "+f"(d[3])
        : "r"(a[0]), "r"(a[1]), "r"(a[2]), "r"(a[3]), "r"(b0), "r"(b1));
}
__device__ __forceinline__ void cpa16(void* dst, const void* src) {
    uint32_t d = smem_u32(dst);
    asm volatile("cp.async.cg.shared.global [%0], [%1], 16;\n" :: "r"(d), "l"(src));
}
#define CP_COMMIT() asm volatile("cp.async.commit_group;\n" ::: "memory")
#define CP_WAIT(n)  asm volatile("cp.async.wait_group %0;\n" :: "n"(n) : "memory")

// ---------------------------------------------------------------------------
// Fused prep: fp32->fp16 rounding of all inputs + kbias tables + null/pad KV
// ---------------------------------------------------------------------------
#define N4_X   (BB*NN*512/4)
#define N4_C   (BB*MM*512/4)
#define N4_WQ  (512*512/4)
#define N4_WKV (512*1024/4)
#define N4_WO  (512*512/4)
#define N4_TOT (N4_X + N4_C + N4_WQ + N4_WKV + N4_WO)
#define NB_ROUND ((N4_TOT + 255) / 256)
#define NB_BIAS  ((BB * MPAD + 255) / 256)
#define NB_KV    (BB * HH)

__global__ void prep_all_kernel(const float* __restrict__ x, const float* __restrict__ ctx,
                                const float* __restrict__ wq, const float* __restrict__ wkv,
                                const float* __restrict__ wo,
                                const unsigned int* __restrict__ cmask,
                                const float* __restrict__ null_key,
                                const float* __restrict__ null_value) {
    int blk = blockIdx.x;
    if (blk < NB_ROUND) {
        int i = blk * 256 + threadIdx.x;
        if (i >= N4_TOT) return;
        const float* src; __half* dst; int off;
        if (i < N4_X)                      { src = x;   dst = g_xh;   off = i; }
        else if (i < N4_X + N4_C)          { src = ctx; dst = g_ch;   off = i - N4_X; }
        else if (i < N4_X + N4_C + N4_WQ)  { src = wq;  dst = g_wqh;  off = i - N4_X - N4_C; }
        else if (i < N4_X + N4_C + N4_WQ + N4_WKV)
                                           { src = wkv; dst = g_wkvh; off = i - N4_X - N4_C - N4_WQ; }
        else                               { src = wo;  dst = g_woh;  off = i - N4_X - N4_C - N4_WQ - N4_WKV; }
        float4 v = ((const float4*)src)[off];
        __half2* d2 = (__half2*)dst;
        d2[2 * off]     = __floats2half2_rn(v.x, v.y);
        d2[2 * off + 1] = __floats2half2_rn(v.z, v.w);
    } else if (blk < NB_ROUND + NB_BIAS) {
        int t = (blk - NB_ROUND) * 256 + threadIdx.x;
        if (t >= BB * MPAD) return;
        int b = t / MPAD, j = t % MPAD;
        float v, v2;
        if (j == 0)        { v = 0.f; v2 = 0.f; }
        else if (j <= MM)  { v = (cmask[b * MM + (j - 1)] != 0u) ? 0.f : -NEG_MAX; v2 = 0.f; }
        else               { v = -INFINITY; v2 = -INFINITY; }
        g_kbias[t] = v;
        g_kbias2[t] = v2;
    } else {
        int bh = blk - NB_ROUND - NB_BIAS;
        __half* Kb = g_Kh + (size_t)bh * MPAD * DHD;
        __half* Vb = g_Vh + (size_t)bh * MPAD * DHD;
        int t = threadIdx.x;
        if (t < DHD) {
            Kb[t] = __float2half_rn(tanhf(null_key[t]));
            Vb[t] = __float2half_rn(null_value[t]);
        }
        for (int idx = t; idx < DHD * (MPAD - MP); idx += 256) {
            int d = idx & 63, jr = idx >> 6;
            Kb[(size_t)(MP + jr) * DHD + d] = __float2half_rn(0.f);
            Vb[(size_t)(MP + jr) * DHD + d] = __float2half_rn(0.f);
        }
    }
}

// ---------------------------------------------------------------------------
// fp16 mma GEMM (R9 version: k-chunk 32, 16 iters, MLP=4, 2 CTA/SM)
// mode 0: Q proj; 1: KV proj; 2: O proj; 3: fused Q+KV dispatch
// ---------------------------------------------------------------------------
__global__ __launch_bounds__(256, 2) void gemm_mma_h(
    const __half* __restrict__ A, const __half* __restrict__ W,
    const float* __restrict__ bias, float* __restrict__ out,
    int Ncols, int mode)
{
    __shared__ __align__(16) __half As[2][128][40];
    __shared__ __align__(16) __half Bs[2][32][136];

    int t = threadIdx.x, lane = t & 31, w = t >> 5;
    int wm = w >> 2, wn = w & 3;
    int g = lane >> 2, cl = lane & 3;
    int row0 = blockIdx.y * 128;
    int col0;
    if (mode == 3) {
        if (blockIdx.x < 4) { A = g_xh; W = g_wqh;  Ncols = 512;  mode = 0; col0 = blockIdx.x * 128; }
        else                { A = g_ch; W = g_wkvh; Ncols = 1024; mode = 1; col0 = (blockIdx.x - 4) * 128; }
    } else {
        col0 = blockIdx.x * 128;
    }

    int ar0 = t >> 2, ac = (t & 3) * 8;
    int br0 = t >> 4, bc = (t & 15) * 8;

    float acc[4][4][4] = {};

    cpa16(&As[0][ar0][ac],      A + (size_t)(row0 + ar0) * 512 + ac);
    cpa16(&As[0][ar0 + 64][ac], A + (size_t)(row0 + ar0 + 64) * 512 + ac);
    cpa16(&Bs[0][br0][bc],      W + (size_t)br0 * Ncols + col0 + bc);
    cpa16(&Bs[0][br0 + 16][bc], W + (size_t)(br0 + 16) * Ncols + col0 + bc);
    CP_COMMIT();

    int a_lr = lane & 15, a_lc = (lane >> 4) * 8;
    int b_lr = (lane & 7) + 8 * ((lane >> 3) & 1), b_lc = 8 * (lane >> 4);

    int p = 0;
    for (int kt = 0; kt < 16; kt++) {
        if (kt < 15) {
            int k0 = (kt + 1) * 32;
            cpa16(&As[1 - p][ar0][ac],      A + (size_t)(row0 + ar0) * 512 + k0 + ac);
            cpa16(&As[1 - p][ar0 + 64][ac], A + (size_t)(row0 + ar0 + 64) * 512 + k0 + ac);
            cpa16(&Bs[1 - p][br0][bc],      W + (size_t)(k0 + br0) * Ncols + col0 + bc);
            cpa16(&Bs[1 - p][br0 + 16][bc], W + (size_t)(k0 + br0 + 16) * Ncols + col0 + bc);
            CP_COMMIT(); CP_WAIT(1);
        } else {
            CP_WAIT(0);
        }
        __syncthreads();

        #pragma unroll
        for (int kc = 0; kc < 2; kc++) {
            uint32_t af[4][4];
            #pragma unroll
            for (int mi = 0; mi < 4; mi++)
                ldsm4(af[mi], smem_u32(&As[p][wm * 64 + mi * 16 + a_lr][kc * 16 + a_lc]));
            #pragma unroll
            for (int np = 0; np < 2; np++) {
                uint32_t bf[4];
                ldsm4t(bf, smem_u32(&Bs[p][kc * 16 + b_lr][wn * 32 + np * 16 + b_lc]));
                #pragma unroll
                for (int mi = 0; mi < 4; mi++) {
                    mma16(acc[mi][np * 2],     af[mi], bf[0], bf[1]);
                    mma16(acc[mi][np * 2 + 1], af[mi], bf[2], bf[3]);
                }
            }
        }
        __syncthreads();
        p ^= 1;
    }

    int bidx = row0 >> 11;
    #pragma unroll
    for (int mi = 0; mi < 4; mi++) {
        int r0 = row0 + wm * 64 + mi * 16 + g;
        int n0r = r0 & 2047;
        #pragma unroll
        for (int ni = 0; ni < 4; ni++) {
            int c = col0 + wn * 32 + ni * 8 + 2 * cl;
            float v0 = acc[mi][ni][0], v1 = acc[mi][ni][1];
            float v2 = acc[mi][ni][2], v3 = acc[mi][ni][3];
            if (mode == 0) {
                int hh = c >> 6, d = c & 63;
                *(__half2*)&g_Qh[(((size_t)bidx * HH + hh) * NN + n0r) * DHD + d] =
                    __floats2half2_rn(tanhf(v0) * 0.125f, tanhf(v1) * 0.125f);
                *(__half2*)&g_Qh[(((size_t)bidx * HH + hh) * NN + n0r + 8) * DHD + d] =
                    __floats2half2_rn(tanhf(v2) * 0.125f, tanhf(v3) * 0.125f);
            } else if (mode == 1) {
                if (c < INNERD) {
                    int hh = c >> 6, d = c & 63;
                    *(__half2*)&g_Kh[(((size_t)bidx * HH + hh) * MPAD + n0r + 1) * DHD + d] =
                        __floats2half2_rn(tanhf(v0), tanhf(v1));
                    *(__half2*)&g_Kh[(((size_t)bidx * HH + hh) * MPAD + n0r + 9) * DHD + d] =
                        __floats2half2_rn(tanhf(v2), tanhf(v3));
                } else {
                    int c2 = c - INNERD;
                    int hh = c2 >> 6, d = c2 & 63;
                    *(__half2*)&g_Vh[(((size_t)bidx * HH + hh) * MPAD + n0r + 1) * DHD + d] =
                        __floats2half2_rn(v0, v1);
                    *(__half2*)&g_Vh[(((size_t)bidx * HH + hh) * MPAD + n0r + 9) * DHD + d] =
                        __floats2half2_rn(v2, v3);
                }
            } else {
                float b0v = bias[c], b1v = bias[c + 1];
                *(float2*)&out[(size_t)r0 * 512 + c]       = make_float2(v0 + b0v, v1 + b1v);
                *(float2*)&out[(size_t)(r0 + 8) * 512 + c] = make_float2(v2 + b0v, v3 + b1v);
            }
        }
    }
}

// ---------------------------------------------------------------------------
// Flash attention: fp16 mma, register P, static-max softmax (scores bounded
// by |s| <= 8 since |q|<=0.125, |k|<=1), per-lane l partials, one bar/tile.
// ---------------------------------------------------------------------------
struct __align__(16) AttnSmemH {
    __half Qs[128][72];       // [q][d]
    __half Kt[2][64][72];     // [j][d]
    __half Vs[2][64][72];     // [j][d]
    float kb[2][64];
    float kbq[2][64];
};

__device__ __forceinline__ void cp_kv_tile(AttnSmemH& s, int buf, const __half* Kb,
                                           const __half* Vb, int j0, int t) {
    #pragma unroll
    for (int i = 0; i < 2; i++) {
        int e = t + i * 256;
        int r = e >> 3, c8 = (e & 7) * 8;
        cpa16(&s.Kt[buf][r][c8], Kb + (size_t)(j0 + r) * DHD + c8);
        cpa16(&s.Vs[buf][r][c8], Vb + (size_t)(j0 + r) * DHD + c8);
    }
}

__global__ __launch_bounds__(256, 2) void attn_kernel(const unsigned int* __restrict__ qmask) {
    extern __shared__ char smem_raw[];
    AttnSmemH& s = *reinterpret_cast<AttnSmemH*>(smem_raw);

    int t = threadIdx.x, lane = t & 31, w = t >> 5;
    int n0 = blockIdx.x * QT;
    int h = blockIdx.y, b = blockIdx.z;
    int bh = b * HH + h;

    const __half* Qb = g_Qh + (size_t)bh * NN * DHD;
    const __half* Kb = g_Kh + (size_t)bh * MPAD * DHD;
    const __half* Vb = g_Vh + (size_t)bh * MPAD * DHD;
    const float* kb_base  = g_kbias  + b * MPAD;
    const float* kbq_base = g_kbias2 + b * MPAD;

    #pragma unroll
    for (int i = 0; i < 4; i++) {
        int e = t + i * 256;
        int q = e >> 3, c8 = (e & 7) * 8;
        *(uint4*)&s.Qs[q][c8] = *(const uint4*)&Qb[(size_t)(n0 + q) * DHD + c8];
    }
    cp_kv_tile(s, 0, Kb, Vb, 0, t);
    CP_COMMIT();
    if (t < 64) {
        s.kb[0][t]  = kb_base[t];
        s.kbq[0][t] = kbq_base[t];
    }
    CP_WAIT(0);
    __syncthreads();

    int g = lane >> 2, cl = lane & 3;
    int row_lo = w * 16 + g;
    int a_lr = lane & 15, a_lc = (lane >> 4) * 8;

    uint32_t aq[4][4];
    #pragma unroll
    for (int ko = 0; ko < 4; ko++)
        ldsm4(aq[ko], smem_u32(&s.Qs[w * 16 + a_lr][ko * 16 + a_lc]));

    int qml = (qmask[b * NN + n0 + row_lo]     != 0u) ? 1 : 0;
    int qmh = (qmask[b * NN + n0 + row_lo + 8] != 0u) ? 1 : 0;

    float l_lo = 0.f, l_hi = 0.f;       // per-lane partials, reduced at end
    float oacc[8][4] = {};
    int p = 0;

    int k_lr = (lane & 7) + 8 * (lane >> 4);
    int k_lc = 8 * ((lane >> 3) & 1);
    int v_lr = (lane & 7) + 8 * ((lane >> 3) & 1);
    int v_lc = 8 * (lane >> 4);

    for (int kt = 0; kt < NTILES; kt++) {
        if (kt < NTILES - 1) {
            int j1 = (kt + 1) * KT;
            cp_kv_tile(s, 1 - p, Kb, Vb, j1, t);
            CP_COMMIT();
            if (t < 64) {
                s.kb[1 - p][t]  = kb_base[j1 + t];
                s.kbq[1 - p][t] = kbq_base[j1 + t];
            }
        }

        // ---- S = Q K^T from buffer p ----
        float sacc[8][4] = {};
        #pragma unroll
        for (int ko = 0; ko < 4; ko++) {
            #pragma unroll
            for (int ntp = 0; ntp < 4; ntp++) {
                uint32_t bf[4];
                ldsm4(bf, smem_u32(&s.Kt[p][ntp * 16 + k_lr][ko * 16 + k_lc]));
                mma16(sacc[ntp * 2],     aq[ko], bf[0], bf[1]);
                mma16(sacc[ntp * 2 + 1], aq[ko], bf[2], bf[3]);
            }
        }

        // ---- mask + static-max softmax: p = exp(x), no running max ----
        uint32_t pf_lo[8], pf_hi[8];
        #pragma unroll
        for (int nt = 0; nt < 8; nt++) {
            int c = nt * 8 + 2 * cl;
            float kb0 = s.kb[p][c], kb1 = s.kb[p][c + 1];
            float kq0 = s.kbq[p][c], kq1 = s.kbq[p][c + 1];
            float x0 = qml ? sacc[nt][0] + kb0 : kq0;
            float x1 = qml ? sacc[nt][1] + kb1 : kq1;
            float x2 = qmh ? sacc[nt][2] + kb0 : kq0;
            float x3 = qmh ? sacc[nt][3] + kb1 : kq1;
            float p0 = __expf(x0);
            float p1 = __expf(x1);
            float p2 = __expf(x2);
            float p3 = __expf(x3);
            __half2 hlo = __floats2half2_rn(p0, p1);
            __half2 hhi = __floats2half2_rn(p2, p3);
            float2 flo = __half22float2(hlo), fhi = __half22float2(hhi);
            l_lo += flo.x + flo.y;
            l_hi += fhi.x + fhi.y;
            pf_lo[nt] = *(uint32_t*)&hlo;
            pf_hi[nt] = *(uint32_t*)&hhi;
        }

        // ---- O += P V from buffer p (no rescale needed) ----
        #pragma unroll
        for (int ko2 = 0; ko2 < 4; ko2++) {
            uint32_t pa[4] = { pf_lo[ko2 * 2], pf_hi[ko2 * 2],
                               pf_lo[ko2 * 2 + 1], pf_hi[ko2 * 2 + 1] };
            #pragma unroll
            for (int ntp = 0; ntp < 4; ntp++) {
                uint32_t bf[4];
                ldsm4t(bf, smem_u32(&s.Vs[p][ko2 * 16 + v_lr][ntp * 16 + v_lc]));
                mma16(oacc[ntp * 2],     pa, bf[0], bf[1]);
                mma16(oacc[ntp * 2 + 1], pa, bf[2], bf[3]);
            }
        }

        if (kt < NTILES - 1) {
            CP_WAIT(0);
            __syncthreads();
        }
        p ^= 1;
    }

    // final l reduction across the 4 lanes sharing each row
    l_lo += __shfl_xor_sync(0xffffffffu, l_lo, 1);
    l_lo += __shfl_xor_sync(0xffffffffu, l_lo, 2);
    l_hi += __shfl_xor_sync(0xffffffffu, l_hi, 1);
    l_hi += __shfl_xor_sync(0xffffffffu, l_hi, 2);

    float li_lo = 1.f / l_lo, li_hi = 1.f / l_hi;
    #pragma unroll
    for (int nt = 0; nt < 8; nt++) {
        int c = nt * 8 + 2 * cl;
        size_t base_lo = ((size_t)b * NN + n0 + row_lo) * INNERD + h * DHD + c;
        size_t base_hi = ((size_t)b * NN + n0 + row_lo + 8) * INNERD + h * DHD + c;
        *(__half2*)&g_Oh[base_lo] = __floats2half2_rn(oacc[nt][0] * li_lo, oacc[nt][1] * li_lo);
        *(__half2*)&g_Oh[base_hi] = __floats2half2_rn(oacc[nt][2] * li_hi, oacc[nt][3] * li_hi);
    }
}

// ---------------------------------------------------------------------------
extern "C" void kernel_launch(void* const* d_in, const int* in_sizes, int n_in,
                              void* d_out, int out_size) {
    const float* x            = (const float*)d_in[0];
    const float* ctx          = (const float*)d_in[1];
    const unsigned int* mask  = (const unsigned int*)d_in[2];
    const unsigned int* cmask = (const unsigned int*)d_in[3];
    const float* Wq  = (const float*)d_in[4];
    const float* Wkv = (const float*)d_in[5];
    const float* Wo  = (const float*)d_in[6];
    const float* bo  = (const float*)d_in[7];
    const float* nk  = (const float*)d_in[8];
    const float* nv  = (const float*)d_in[9];
    float* out = (float*)d_out;

    static int inited = 0;
    if (!inited) {
        cudaFuncSetAttribute(attn_kernel, cudaFuncAttributeMaxDynamicSharedMemorySize,
                             (int)sizeof(AttnSmemH));
        inited = 1;
    }

    __half *oh, *woh;
    cudaGetSymbolAddress((void**)&oh,  g_Oh);
    cudaGetSymbolAddress((void**)&woh, g_woh);

    prep_all_kernel<<<NB_ROUND + NB_BIAS + NB_KV, 256>>>(x, ctx, Wq, Wkv, Wo, cmask, nk, nv);

    dim3 gqkv(12, 64);
    gemm_mma_h<<<gqkv, 256>>>(nullptr, nullptr, nullptr, nullptr, 0, 3);

    dim3 ga(NN / QT, HH, BB);                        // (16, 8, 4)
    attn_kernel<<<ga, 256, sizeof(AttnSmemH)>>>(mask);

    dim3 g2(512 / 128, (BB * NN) / 128);             // (4, 64)
    gemm_mma_h<<<g2, 256>>>(oh, woh, bo, out, 512, 2);
}

// round 12
// speedup vs baseline: 1.2078x; 1.0243x over previous
#include <cuda_runtime.h>
#include <cuda_fp16.h>
#include <math.h>
#include <stdint.h>

#define BB 4
#define NN 2048
#define MM 2048
#define HH 8
#define DHD 64
#define INNERD 512
#define MP 2049
#define MPAD 2176          // 34 * 64
#define KT 64
#define QT 128
#define NTILES (MPAD / KT) // 34
#define NEG_MAX 3.402823466e38f

// Scratch (device globals; no allocation allowed)
__device__ __half g_Qh[(size_t)BB*HH*NN*DHD];    // [b,h,n,d]  tanh(q)*scale
__device__ __half g_Kh[(size_t)BB*HH*MPAD*DHD];  // [b,h,j,d]  tanh(k), j=0 null
__device__ __half g_Vh[(size_t)BB*HH*MPAD*DHD];  // [b,h,j,d]
__device__ __half g_Oh[(size_t)BB*NN*INNERD];    // [b,n,h*d]
__device__ float  g_kbias[BB*MPAD];              // 0 attend / -FLT_MAX masked / -INF pad
__device__ float  g_kbias2[BB*MPAD];             // 0 non-pad / -INF pad (masked-query rows)
__device__ __half g_xh[(size_t)BB*NN*512];
__device__ __half g_ch[(size_t)BB*MM*512];
__device__ __half g_wqh[512*512];
__device__ __half g_wkvh[512*1024];
__device__ __half g_woh[512*512];

__device__ __forceinline__ uint32_t smem_u32(const void* p) {
    return (uint32_t)__cvta_generic_to_shared(p);
}
__device__ __forceinline__ void ldsm4(uint32_t* r, uint32_t a) {
    asm volatile("ldmatrix.sync.aligned.m8n8.x4.shared.b16 {%0,%1,%2,%3}, [%4];"
        : "=r"(r[0]), "=r"(r[1]), "=r"(r[2]), "=r"(r[3]) : "r"(a));
}
__device__ __forceinline__ void ldsm4t(uint32_t* r, uint32_t a) {
    asm volatile("ldmatrix.sync.aligned.m8n8.x4.trans.shared.b16 {%0,%1,%2,%3}, [%4];"
        : "=r"(r[0]), "=r"(r[1]), "=r"(r[2]), "=r"(r[3]) : "r"(a));
}
__device__ __forceinline__ void mma16(float* d, const uint32_t* a, uint32_t b0, uint32_t b1) {
    asm volatile(
        "mma.sync.aligned.m16n8k16.row.col.f32.f16.f16.f32 "
        "{%0,%1,%2,%3}, {%4,%5,%6,%7}, {%8,%9}, {%0,%1,%2,%3};"
        : "+f"(d[0]), "+f"(d[1]), "+f"(d[2]), "+f"(d[3])
        : "r"(a[0]), "r"(a[1]), "r"(a[2]), "r"(a[3]), "r"(b0), "r"(b1));
}
__device__ __forceinline__ void cpa16(void* dst, const void* src) {
    uint32_t d = smem_u32(dst);
    asm volatile("cp.async.cg.shared.global [%0], [%1], 16;\n" :: "r"(d), "l"(src));
}
#define CP_COMMIT() asm volatile("cp.async.commit_group;\n" ::: "memory")
#define CP_WAIT(n)  asm volatile("cp.async.wait_group %0;\n" :: "n"(n) : "memory")

// ---------------------------------------------------------------------------
// Fused prep: fp32->fp16 rounding of all inputs + kbias tables + null/pad KV
// ---------------------------------------------------------------------------
#define N4_X   (BB*NN*512/4)
#define N4_C   (BB*MM*512/4)
#define N4_WQ  (512*512/4)
#define N4_WKV (512*1024/4)
#define N4_WO  (512*512/4)
#define N4_TOT (N4_X + N4_C + N4_WQ + N4_WKV + N4_WO)
#define NB_ROUND ((N4_TOT + 255) / 256)
#define NB_BIAS  ((BB * MPAD + 255) / 256)
#define NB_KV    (BB * HH)

__global__ void prep_all_kernel(const float* __restrict__ x, const float* __restrict__ ctx,
                                const float* __restrict__ wq, const float* __restrict__ wkv,
                                const float* __restrict__ wo,
                                const unsigned int* __restrict__ cmask,
                                const float* __restrict__ null_key,
                                const float* __restrict__ null_value) {
    int blk = blockIdx.x;
    if (blk < NB_ROUND) {
        int i = blk * 256 + threadIdx.x;
        if (i >= N4_TOT) return;
        const float* src; __half* dst; int off;
        if (i < N4_X)                      { src = x;   dst = g_xh;   off = i; }
        else if (i < N4_X + N4_C)          { src = ctx; dst = g_ch;   off = i - N4_X; }
        else if (i < N4_X + N4_C + N4_WQ)  { src = wq;  dst = g_wqh;  off = i - N4_X - N4_C; }
        else if (i < N4_X + N4_C + N4_WQ + N4_WKV)
                                           { src = wkv; dst = g_wkvh; off = i - N4_X - N4_C - N4_WQ; }
        else                               { src = wo;  dst = g_woh;  off = i - N4_X - N4_C - N4_WQ - N4_WKV; }
        float4 v = ((const float4*)src)[off];
        __half2* d2 = (__half2*)dst;
        d2[2 * off]     = __floats2half2_rn(v.x, v.y);
        d2[2 * off + 1] = __floats2half2_rn(v.z, v.w);
    } else if (blk < NB_ROUND + NB_BIAS) {
        int t = (blk - NB_ROUND) * 256 + threadIdx.x;
        if (t >= BB * MPAD) return;
        int b = t / MPAD, j = t % MPAD;
        float v, v2;
        if (j == 0)        { v = 0.f; v2 = 0.f; }
        else if (j <= MM)  { v = (cmask[b * MM + (j - 1)] != 0u) ? 0.f : -NEG_MAX; v2 = 0.f; }
        else               { v = -INFINITY; v2 = -INFINITY; }
        g_kbias[t] = v;
        g_kbias2[t] = v2;
    } else {
        int bh = blk - NB_ROUND - NB_BIAS;
        __half* Kb = g_Kh + (size_t)bh * MPAD * DHD;
        __half* Vb = g_Vh + (size_t)bh * MPAD * DHD;
        int t = threadIdx.x;
        if (t < DHD) {
            Kb[t] = __float2half_rn(tanhf(null_key[t]));
            Vb[t] = __float2half_rn(null_value[t]);
        }
        for (int idx = t; idx < DHD * (MPAD - MP); idx += 256) {
            int d = idx & 63, jr = idx >> 6;
            Kb[(size_t)(MP + jr) * DHD + d] = __float2half_rn(0.f);
            Vb[(size_t)(MP + jr) * DHD + d] = __float2half_rn(0.f);
        }
    }
}

// ---------------------------------------------------------------------------
// fp16 mma GEMM: k-chunk 32, ONE __syncthreads per k-iter (prefetch-first
// schedule, copy overlapped with full compute stage). 2 CTA/SM.
// mode 0: Q proj; 1: KV proj; 2: O proj; 3: fused Q+KV dispatch
// ---------------------------------------------------------------------------
__global__ __launch_bounds__(256, 2) void gemm_mma_h(
    const __half* __restrict__ A, const __half* __restrict__ W,
    const float* __restrict__ bias, float* __restrict__ out,
    int Ncols, int mode)
{
    __shared__ __align__(16) __half As[2][128][40];
    __shared__ __align__(16) __half Bs[2][32][136];

    int t = threadIdx.x, lane = t & 31, w = t >> 5;
    int wm = w >> 2, wn = w & 3;
    int g = lane >> 2, cl = lane & 3;
    int row0 = blockIdx.y * 128;
    int col0;
    if (mode == 3) {
        if (blockIdx.x < 4) { A = g_xh; W = g_wqh;  Ncols = 512;  mode = 0; col0 = blockIdx.x * 128; }
        else                { A = g_ch; W = g_wkvh; Ncols = 1024; mode = 1; col0 = (blockIdx.x - 4) * 128; }
    } else {
        col0 = blockIdx.x * 128;
    }

    int ar0 = t >> 2, ac = (t & 3) * 8;
    int br0 = t >> 4, bc = (t & 15) * 8;

    float acc[4][4][4] = {};

    // stage 0
    cpa16(&As[0][ar0][ac],      A + (size_t)(row0 + ar0) * 512 + ac);
    cpa16(&As[0][ar0 + 64][ac], A + (size_t)(row0 + ar0 + 64) * 512 + ac);
    cpa16(&Bs[0][br0][bc],      W + (size_t)br0 * Ncols + col0 + bc);
    cpa16(&Bs[0][br0 + 16][bc], W + (size_t)(br0 + 16) * Ncols + col0 + bc);
    CP_COMMIT();
    CP_WAIT(0);
    __syncthreads();

    int a_lr = lane & 15, a_lc = (lane >> 4) * 8;
    int b_lr = (lane & 7) + 8 * ((lane >> 3) & 1), b_lc = 8 * (lane >> 4);

    int p = 0;
    for (int kt = 0; kt < 16; kt++) {
        // prefetch next stage into buffer 1-p (protected by previous bottom sync)
        if (kt < 15) {
            int k0 = (kt + 1) * 32;
            cpa16(&As[1 - p][ar0][ac],      A + (size_t)(row0 + ar0) * 512 + k0 + ac);
            cpa16(&As[1 - p][ar0 + 64][ac], A + (size_t)(row0 + ar0 + 64) * 512 + k0 + ac);
            cpa16(&Bs[1 - p][br0][bc],      W + (size_t)(k0 + br0) * Ncols + col0 + bc);
            cpa16(&Bs[1 - p][br0 + 16][bc], W + (size_t)(k0 + br0 + 16) * Ncols + col0 + bc);
            CP_COMMIT();
        }

        // compute stage p
        #pragma unroll
        for (int kc = 0; kc < 2; kc++) {
            uint32_t af[4][4];
            #pragma unroll
            for (int mi = 0; mi < 4; mi++)
                ldsm4(af[mi], smem_u32(&As[p][wm * 64 + mi * 16 + a_lr][kc * 16 + a_lc]));
            #pragma unroll
            for (int np = 0; np < 2; np++) {
                uint32_t bf[4];
                ldsm4t(bf, smem_u32(&Bs[p][kc * 16 + b_lr][wn * 32 + np * 16 + b_lc]));
                #pragma unroll
                for (int mi = 0; mi < 4; mi++) {
                    mma16(acc[mi][np * 2],     af[mi], bf[0], bf[1]);
                    mma16(acc[mi][np * 2 + 1], af[mi], bf[2], bf[3]);
                }
            }
        }

        if (kt < 15) {
            CP_WAIT(0);
            __syncthreads();
        }
        p ^= 1;
    }

    int bidx = row0 >> 11;
    #pragma unroll
    for (int mi = 0; mi < 4; mi++) {
        int r0 = row0 + wm * 64 + mi * 16 + g;
        int n0r = r0 & 2047;
        #pragma unroll
        for (int ni = 0; ni < 4; ni++) {
            int c = col0 + wn * 32 + ni * 8 + 2 * cl;
            float v0 = acc[mi][ni][0], v1 = acc[mi][ni][1];
            float v2 = acc[mi][ni][2], v3 = acc[mi][ni][3];
            if (mode == 0) {
                int hh = c >> 6, d = c & 63;
                *(__half2*)&g_Qh[(((size_t)bidx * HH + hh) * NN + n0r) * DHD + d] =
                    __floats2half2_rn(tanhf(v0) * 0.125f, tanhf(v1) * 0.125f);
                *(__half2*)&g_Qh[(((size_t)bidx * HH + hh) * NN + n0r + 8) * DHD + d] =
                    __floats2half2_rn(tanhf(v2) * 0.125f, tanhf(v3) * 0.125f);
            } else if (mode == 1) {
                if (c < INNERD) {
                    int hh = c >> 6, d = c & 63;
                    *(__half2*)&g_Kh[(((size_t)bidx * HH + hh) * MPAD + n0r + 1) * DHD + d] =
                        __floats2half2_rn(tanhf(v0), tanhf(v1));
                    *(__half2*)&g_Kh[(((size_t)bidx * HH + hh) * MPAD + n0r + 9) * DHD + d] =
                        __floats2half2_rn(tanhf(v2), tanhf(v3));
                } else {
                    int c2 = c - INNERD;
                    int hh = c2 >> 6, d = c2 & 63;
                    *(__half2*)&g_Vh[(((size_t)bidx * HH + hh) * MPAD + n0r + 1) * DHD + d] =
                        __floats2half2_rn(v0, v1);
                    *(__half2*)&g_Vh[(((size_t)bidx * HH + hh) * MPAD + n0r + 9) * DHD + d] =
                        __floats2half2_rn(v2, v3);
                }
            } else {
                float b0v = bias[c], b1v = bias[c + 1];
                *(float2*)&out[(size_t)r0 * 512 + c]       = make_float2(v0 + b0v, v1 + b1v);
                *(float2*)&out[(size_t)(r0 + 8) * 512 + c] = make_float2(v2 + b0v, v3 + b1v);
            }
        }
    }
}

// ---------------------------------------------------------------------------
// Flash attention: fp16 mma, register P, static-max softmax, one bar/tile.
// (unchanged from R11)
// ---------------------------------------------------------------------------
struct __align__(16) AttnSmemH {
    __half Qs[128][72];       // [q][d]
    __half Kt[2][64][72];     // [j][d]
    __half Vs[2][64][72];     // [j][d]
    float kb[2][64];
    float kbq[2][64];
};

__device__ __forceinline__ void cp_kv_tile(AttnSmemH& s, int buf, const __half* Kb,
                                           const __half* Vb, int j0, int t) {
    #pragma unroll
    for (int i = 0; i < 2; i++) {
        int e = t + i * 256;
        int r = e >> 3, c8 = (e & 7) * 8;
        cpa16(&s.Kt[buf][r][c8], Kb + (size_t)(j0 + r) * DHD + c8);
        cpa16(&s.Vs[buf][r][c8], Vb + (size_t)(j0 + r) * DHD + c8);
    }
}

__global__ __launch_bounds__(256, 2) void attn_kernel(const unsigned int* __restrict__ qmask) {
    extern __shared__ char smem_raw[];
    AttnSmemH& s = *reinterpret_cast<AttnSmemH*>(smem_raw);

    int t = threadIdx.x, lane = t & 31, w = t >> 5;
    int n0 = blockIdx.x * QT;
    int h = blockIdx.y, b = blockIdx.z;
    int bh = b * HH + h;

    const __half* Qb = g_Qh + (size_t)bh * NN * DHD;
    const __half* Kb = g_Kh + (size_t)bh * MPAD * DHD;
    const __half* Vb = g_Vh + (size_t)bh * MPAD * DHD;
    const float* kb_base  = g_kbias  + b * MPAD;
    const float* kbq_base = g_kbias2 + b * MPAD;

    #pragma unroll
    for (int i = 0; i < 4; i++) {
        int e = t + i * 256;
        int q = e >> 3, c8 = (e & 7) * 8;
        *(uint4*)&s.Qs[q][c8] = *(const uint4*)&Qb[(size_t)(n0 + q) * DHD + c8];
    }
    cp_kv_tile(s, 0, Kb, Vb, 0, t);
    CP_COMMIT();
    if (t < 64) {
        s.kb[0][t]  = kb_base[t];
        s.kbq[0][t] = kbq_base[t];
    }
    CP_WAIT(0);
    __syncthreads();

    int g = lane >> 2, cl = lane & 3;
    int row_lo = w * 16 + g;
    int a_lr = lane & 15, a_lc = (lane >> 4) * 8;

    uint32_t aq[4][4];
    #pragma unroll
    for (int ko = 0; ko < 4; ko++)
        ldsm4(aq[ko], smem_u32(&s.Qs[w * 16 + a_lr][ko * 16 + a_lc]));

    int qml = (qmask[b * NN + n0 + row_lo]     != 0u) ? 1 : 0;
    int qmh = (qmask[b * NN + n0 + row_lo + 8] != 0u) ? 1 : 0;

    float l_lo = 0.f, l_hi = 0.f;
    float oacc[8][4] = {};
    int p = 0;

    int k_lr = (lane & 7) + 8 * (lane >> 4);
    int k_lc = 8 * ((lane >> 3) & 1);
    int v_lr = (lane & 7) + 8 * ((lane >> 3) & 1);
    int v_lc = 8 * (lane >> 4);

    for (int kt = 0; kt < NTILES; kt++) {
        if (kt < NTILES - 1) {
            int j1 = (kt + 1) * KT;
            cp_kv_tile(s, 1 - p, Kb, Vb, j1, t);
            CP_COMMIT();
            if (t < 64) {
                s.kb[1 - p][t]  = kb_base[j1 + t];
                s.kbq[1 - p][t] = kbq_base[j1 + t];
            }
        }

        // ---- S = Q K^T from buffer p ----
        float sacc[8][4] = {};
        #pragma unroll
        for (int ko = 0; ko < 4; ko++) {
            #pragma unroll
            for (int ntp = 0; ntp < 4; ntp++) {
                uint32_t bf[4];
                ldsm4(bf, smem_u32(&s.Kt[p][ntp * 16 + k_lr][ko * 16 + k_lc]));
                mma16(sacc[ntp * 2],     aq[ko], bf[0], bf[1]);
                mma16(sacc[ntp * 2 + 1], aq[ko], bf[2], bf[3]);
            }
        }

        // ---- mask + static-max softmax: p = exp(x) ----
        uint32_t pf_lo[8], pf_hi[8];
        #pragma unroll
        for (int nt = 0; nt < 8; nt++) {
            int c = nt * 8 + 2 * cl;
            float kb0 = s.kb[p][c], kb1 = s.kb[p][c + 1];
            float kq0 = s.kbq[p][c], kq1 = s.kbq[p][c + 1];
            float x0 = qml ? sacc[nt][0] + kb0 : kq0;
            float x1 = qml ? sacc[nt][1] + kb1 : kq1;
            float x2 = qmh ? sacc[nt][2] + kb0 : kq0;
            float x3 = qmh ? sacc[nt][3] + kb1 : kq1;
            float p0 = __expf(x0);
            float p1 = __expf(x1);
            float p2 = __expf(x2);
            float p3 = __expf(x3);
            __half2 hlo = __floats2half2_rn(p0, p1);
            __half2 hhi = __floats2half2_rn(p2, p3);
            float2 flo = __half22float2(hlo), fhi = __half22float2(hhi);
            l_lo += flo.x + flo.y;
            l_hi += fhi.x + fhi.y;
            pf_lo[nt] = *(uint32_t*)&hlo;
            pf_hi[nt] = *(uint32_t*)&hhi;
        }

        // ---- O += P V from buffer p ----
        #pragma unroll
        for (int ko2 = 0; ko2 < 4; ko2++) {
            uint32_t pa[4] = { pf_lo[ko2 * 2], pf_hi[ko2 * 2],
                               pf_lo[ko2 * 2 + 1], pf_hi[ko2 * 2 + 1] };
            #pragma unroll
            for (int ntp = 0; ntp < 4; ntp++) {
                uint32_t bf[4];
                ldsm4t(bf, smem_u32(&s.Vs[p][ko2 * 16 + v_lr][ntp * 16 + v_lc]));
                mma16(oacc[ntp * 2],     pa, bf[0], bf[1]);
                mma16(oacc[ntp * 2 + 1], pa, bf[2], bf[3]);
            }
        }

        if (kt < NTILES - 1) {
            CP_WAIT(0);
            __syncthreads();
        }
        p ^= 1;
    }

    l_lo += __shfl_xor_sync(0xffffffffu, l_lo, 1);
    l_lo += __shfl_xor_sync(0xffffffffu, l_lo, 2);
    l_hi += __shfl_xor_sync(0xffffffffu, l_hi, 1);
    l_hi += __shfl_xor_sync(0xffffffffu, l_hi, 2);

    float li_lo = 1.f / l_lo, li_hi = 1.f / l_hi;
    #pragma unroll
    for (int nt = 0; nt < 8; nt++) {
        int c = nt * 8 + 2 * cl;
        size_t base_lo = ((size_t)b * NN + n0 + row_lo) * INNERD + h * DHD + c;
        size_t base_hi = ((size_t)b * NN + n0 + row_lo + 8) * INNERD + h * DHD + c;
        *(__half2*)&g_Oh[base_lo] = __floats2half2_rn(oacc[nt][0] * li_lo, oacc[nt][1] * li_lo);
        *(__half2*)&g_Oh[base_hi] = __floats2half2_rn(oacc[nt][2] * li_hi, oacc[nt][3] * li_hi);
    }
}

// ---------------------------------------------------------------------------
extern "C" void kernel_launch(void* const* d_in, const int* in_sizes, int n_in,
                              void* d_out, int out_size) {
    const float* x            = (const float*)d_in[0];
    const float* ctx          = (const float*)d_in[1];
    const unsigned int* mask  = (const unsigned int*)d_in[2];
    const unsigned int* cmask = (const unsigned int*)d_in[3];
    const float* Wq  = (const float*)d_in[4];
    const float* Wkv = (const float*)d_in[5];
    const float* Wo  = (const float*)d_in[6];
    const float* bo  = (const float*)d_in[7];
    const float* nk  = (const float*)d_in[8];
    const float* nv  = (const float*)d_in[9];
    float* out = (float*)d_out;

    static int inited = 0;
    if (!inited) {
        cudaFuncSetAttribute(attn_kernel, cudaFuncAttributeMaxDynamicSharedMemorySize,
                             (int)sizeof(AttnSmemH));
        inited = 1;
    }

    __half *oh, *woh;
    cudaGetSymbolAddress((void**)&oh,  g_Oh);
    cudaGetSymbolAddress((void**)&woh, g_woh);

    prep_all_kernel<<<NB_ROUND + NB_BIAS + NB_KV, 256>>>(x, ctx, Wq, Wkv, Wo, cmask, nk, nv);

    dim3 gqkv(12, 64);
    gemm_mma_h<<<gqkv, 256>>>(nullptr, nullptr, nullptr, nullptr, 0, 3);

    dim3 ga(NN / QT, HH, BB);                        // (16, 8, 4)
    attn_kernel<<<ga, 256, sizeof(AttnSmemH)>>>(mask);

    dim3 g2(512 / 128, (BB * NN) / 128);             // (4, 64)
    gemm_mma_h<<<g2, 256>>>(oh, woh, bo, out, 512, 2);
}

// round 13
// speedup vs baseline: 1.3330x; 1.1036x over previous
#include <cuda_runtime.h>
#include <cuda_fp16.h>
#include <math.h>
#include <stdint.h>

#define BB 4
#define NN 2048
#define MM 2048
#define HH 8
#define DHD 64
#define INNERD 512
#define MP 2049
#define MPAD 2176          // 34 * 64
#define KT 64
#define QT 128
#define NTILES (MPAD / KT) // 34
#define SCALEQ 0.18033688f // 0.125 * log2(e): scores come out in log2 domain

// Scratch (device globals; no allocation allowed)
__device__ __half g_Qh[(size_t)BB*HH*NN*DHD];    // [b,h,n,d]  tanh(q)*0.125*log2e
__device__ __half g_Kh[(size_t)BB*HH*MPAD*DHD];  // [b,h,j,d]  tanh(k), j=0 null, pad 0
__device__ __half g_Vh[(size_t)BB*HH*MPAD*DHD];  // [b,h,j,d]
__device__ __half g_Oh[(size_t)BB*NN*INNERD];    // [b,n,h*d]
__device__ __half g_kmh[BB*MPAD];                // 1 attendable / 0 masked / 0 pad
__device__ __half g_kmh2[BB*MPAD];               // 1 non-pad / 0 pad  (masked-query rows)
__device__ __half g_xh[(size_t)BB*NN*512];
__device__ __half g_ch[(size_t)BB*MM*512];
__device__ __half g_wqh[512*512];
__device__ __half g_wkvh[512*1024];
__device__ __half g_woh[512*512];

__device__ __forceinline__ uint32_t smem_u32(const void* p) {
    return (uint32_t)__cvta_generic_to_shared(p);
}
__device__ __forceinline__ void ldsm4(uint32_t* r, uint32_t a) {
    asm volatile("ldmatrix.sync.aligned.m8n8.x4.shared.b16 {%0,%1,%2,%3}, [%4];"
        : "=r"(r[0]), "=r"(r[1]), "=r"(r[2]), "=r"(r[3]) : "r"(a));
}
__device__ __forceinline__ void ldsm4t(uint32_t* r, uint32_t a) {
    asm volatile("ldmatrix.sync.aligned.m8n8.x4.trans.shared.b16 {%0,%1,%2,%3}, [%4];"
        : "=r"(r[0]), "=r"(r[1]), "=r"(r[2]), "=r"(r[3]) : "r"(a));
}
__device__ __forceinline__ void mma16(float* d, const uint32_t* a, uint32_t b0, uint32_t b1) {
    asm volatile(
        "mma.sync.aligned.m16n8k16.row.col.f32.f16.f16.f32 "
        "{%0,%1,%2,%3}, {%4,%5,%6,%7}, {%8,%9}, {%0,%1,%2,%3};"
        : "+f"(d[0]), "+f"(d[1]), "+f"(d[2]), "+f"(d[3])
        : "r"(a[0]), "r"(a[1]), "r"(a[2]), "r"(a[3]), "r"(b0), "r"(b1));
}
__device__ __forceinline__ void cpa16(void* dst, const void* src) {
    uint32_t d = smem_u32(dst);
    asm volatile("cp.async.cg.shared.global [%0], [%1], 16;\n" :: "r"(d), "l"(src));
}
__device__ __forceinline__ uint32_t ex2_f16x2(uint32_t x) {
    uint32_t r;
    asm("ex2.approx.f16x2 %0, %1;" : "=r"(r) : "r"(x));
    return r;
}
#define CP_COMMIT() asm volatile("cp.async.commit_group;\n" ::: "memory")
#define CP_WAIT(n)  asm volatile("cp.async.wait_group %0;\n" :: "n"(n) : "memory")

// ---------------------------------------------------------------------------
// Fused prep: fp32->fp16 rounding (MLP=4 per thread) + mask tables + null/pad
// ---------------------------------------------------------------------------
#define N4_X   (BB*NN*512/4)
#define N4_C   (BB*MM*512/4)
#define N4_WQ  (512*512/4)
#define N4_WKV (512*1024/4)
#define N4_WO  (512*512/4)
#define N4_TOT (N4_X + N4_C + N4_WQ + N4_WKV + N4_WO)
#define NB_ROUND (N4_TOT / 1024)                 // segment sizes all multiples of 1024
#define NB_BIAS  ((BB * MPAD + 255) / 256)
#define NB_KV    (BB * HH)

__global__ void prep_all_kernel(const float* __restrict__ x, const float* __restrict__ ctx,
                                const float* __restrict__ wq, const float* __restrict__ wkv,
                                const float* __restrict__ wo,
                                const unsigned int* __restrict__ cmask,
                                const float* __restrict__ null_key,
                                const float* __restrict__ null_value) {
    int blk = blockIdx.x;
    if (blk < NB_ROUND) {
        int i0 = blk * 1024;
        const float* src; __half* dst; int seg0;
        if (i0 < N4_X)                               { src = x;   dst = g_xh;   seg0 = 0; }
        else if (i0 < N4_X + N4_C)                   { src = ctx; dst = g_ch;   seg0 = N4_X; }
        else if (i0 < N4_X + N4_C + N4_WQ)           { src = wq;  dst = g_wqh;  seg0 = N4_X + N4_C; }
        else if (i0 < N4_X + N4_C + N4_WQ + N4_WKV)  { src = wkv; dst = g_wkvh; seg0 = N4_X + N4_C + N4_WQ; }
        else                                         { src = wo;  dst = g_woh;  seg0 = N4_X + N4_C + N4_WQ + N4_WKV; }
        int off0 = i0 - seg0 + threadIdx.x;
        float4 v[4];
        #pragma unroll
        for (int j = 0; j < 4; j++)
            v[j] = ((const float4*)src)[off0 + j * 256];
        #pragma unroll
        for (int j = 0; j < 4; j++) {
            __half2 a = __floats2half2_rn(v[j].x, v[j].y);
            __half2 b = __floats2half2_rn(v[j].z, v[j].w);
            uint2 o;
            o.x = *(uint32_t*)&a;
            o.y = *(uint32_t*)&b;
            ((uint2*)dst)[off0 + j * 256] = o;
        }
    } else if (blk < NB_ROUND + NB_BIAS) {
        int t = (blk - NB_ROUND) * 256 + threadIdx.x;
        if (t >= BB * MPAD) return;
        int b = t / MPAD, j = t % MPAD;
        float m, m2;
        if (j == 0)        { m = 1.f; m2 = 1.f; }
        else if (j <= MM)  { m = (cmask[b * MM + (j - 1)] != 0u) ? 1.f : 0.f; m2 = 1.f; }
        else               { m = 0.f; m2 = 0.f; }
        g_kmh[t]  = __float2half_rn(m);
        g_kmh2[t] = __float2half_rn(m2);
    } else {
        int bh = blk - NB_ROUND - NB_BIAS;
        __half* Kb = g_Kh + (size_t)bh * MPAD * DHD;
        __half* Vb = g_Vh + (size_t)bh * MPAD * DHD;
        int t = threadIdx.x;
        if (t < DHD) {
            Kb[t] = __float2half_rn(tanhf(null_key[t]));
            Vb[t] = __float2half_rn(null_value[t]);
        }
        for (int idx = t; idx < DHD * (MPAD - MP); idx += 256) {
            int d = idx & 63, jr = idx >> 6;
            Kb[(size_t)(MP + jr) * DHD + d] = __float2half_rn(0.f);
            Vb[(size_t)(MP + jr) * DHD + d] = __float2half_rn(0.f);
        }
    }
}

// ---------------------------------------------------------------------------
// fp16 mma GEMM (R12 version: k-chunk 32, single sync/iter, 2 CTA/SM)
// mode 0: Q proj; 1: KV proj; 2: O proj; 3: fused Q+KV dispatch
// ---------------------------------------------------------------------------
__global__ __launch_bounds__(256, 2) void gemm_mma_h(
    const __half* __restrict__ A, const __half* __restrict__ W,
    const float* __restrict__ bias, float* __restrict__ out,
    int Ncols, int mode)
{
    __shared__ __align__(16) __half As[2][128][40];
    __shared__ __align__(16) __half Bs[2][32][136];

    int t = threadIdx.x, lane = t & 31, w = t >> 5;
    int wm = w >> 2, wn = w & 3;
    int g = lane >> 2, cl = lane & 3;
    int row0 = blockIdx.y * 128;
    int col0;
    if (mode == 3) {
        if (blockIdx.x < 4) { A = g_xh; W = g_wqh;  Ncols = 512;  mode = 0; col0 = blockIdx.x * 128; }
        else                { A = g_ch; W = g_wkvh; Ncols = 1024; mode = 1; col0 = (blockIdx.x - 4) * 128; }
    } else {
        col0 = blockIdx.x * 128;
    }

    int ar0 = t >> 2, ac = (t & 3) * 8;
    int br0 = t >> 4, bc = (t & 15) * 8;

    float acc[4][4][4] = {};

    cpa16(&As[0][ar0][ac],      A + (size_t)(row0 + ar0) * 512 + ac);
    cpa16(&As[0][ar0 + 64][ac], A + (size_t)(row0 + ar0 + 64) * 512 + ac);
    cpa16(&Bs[0][br0][bc],      W + (size_t)br0 * Ncols + col0 + bc);
    cpa16(&Bs[0][br0 + 16][bc], W + (size_t)(br0 + 16) * Ncols + col0 + bc);
    CP_COMMIT();
    CP_WAIT(0);
    __syncthreads();

    int a_lr = lane & 15, a_lc = (lane >> 4) * 8;
    int b_lr = (lane & 7) + 8 * ((lane >> 3) & 1), b_lc = 8 * (lane >> 4);

    int p = 0;
    for (int kt = 0; kt < 16; kt++) {
        if (kt < 15) {
            int k0 = (kt + 1) * 32;
            cpa16(&As[1 - p][ar0][ac],      A + (size_t)(row0 + ar0) * 512 + k0 + ac);
            cpa16(&As[1 - p][ar0 + 64][ac], A + (size_t)(row0 + ar0 + 64) * 512 + k0 + ac);
            cpa16(&Bs[1 - p][br0][bc],      W + (size_t)(k0 + br0) * Ncols + col0 + bc);
            cpa16(&Bs[1 - p][br0 + 16][bc], W + (size_t)(k0 + br0 + 16) * Ncols + col0 + bc);
            CP_COMMIT();
        }

        #pragma unroll
        for (int kc = 0; kc < 2; kc++) {
            uint32_t af[4][4];
            #pragma unroll
            for (int mi = 0; mi < 4; mi++)
                ldsm4(af[mi], smem_u32(&As[p][wm * 64 + mi * 16 + a_lr][kc * 16 + a_lc]));
            #pragma unroll
            for (int np = 0; np < 2; np++) {
                uint32_t bf[4];
                ldsm4t(bf, smem_u32(&Bs[p][kc * 16 + b_lr][wn * 32 + np * 16 + b_lc]));
                #pragma unroll
                for (int mi = 0; mi < 4; mi++) {
                    mma16(acc[mi][np * 2],     af[mi], bf[0], bf[1]);
                    mma16(acc[mi][np * 2 + 1], af[mi], bf[2], bf[3]);
                }
            }
        }

        if (kt < 15) {
            CP_WAIT(0);
            __syncthreads();
        }
        p ^= 1;
    }

    int bidx = row0 >> 11;
    #pragma unroll
    for (int mi = 0; mi < 4; mi++) {
        int r0 = row0 + wm * 64 + mi * 16 + g;
        int n0r = r0 & 2047;
        #pragma unroll
        for (int ni = 0; ni < 4; ni++) {
            int c = col0 + wn * 32 + ni * 8 + 2 * cl;
            float v0 = acc[mi][ni][0], v1 = acc[mi][ni][1];
            float v2 = acc[mi][ni][2], v3 = acc[mi][ni][3];
            if (mode == 0) {
                int hh = c >> 6, d = c & 63;
                *(__half2*)&g_Qh[(((size_t)bidx * HH + hh) * NN + n0r) * DHD + d] =
                    __floats2half2_rn(tanhf(v0) * SCALEQ, tanhf(v1) * SCALEQ);
                *(__half2*)&g_Qh[(((size_t)bidx * HH + hh) * NN + n0r + 8) * DHD + d] =
                    __floats2half2_rn(tanhf(v2) * SCALEQ, tanhf(v3) * SCALEQ);
            } else if (mode == 1) {
                if (c < INNERD) {
                    int hh = c >> 6, d = c & 63;
                    *(__half2*)&g_Kh[(((size_t)bidx * HH + hh) * MPAD + n0r + 1) * DHD + d] =
                        __floats2half2_rn(tanhf(v0), tanhf(v1));
                    *(__half2*)&g_Kh[(((size_t)bidx * HH + hh) * MPAD + n0r + 9) * DHD + d] =
                        __floats2half2_rn(tanhf(v2), tanhf(v3));
                } else {
                    int c2 = c - INNERD;
                    int hh = c2 >> 6, d = c2 & 63;
                    *(__half2*)&g_Vh[(((size_t)bidx * HH + hh) * MPAD + n0r + 1) * DHD + d] =
                        __floats2half2_rn(v0, v1);
                    *(__half2*)&g_Vh[(((size_t)bidx * HH + hh) * MPAD + n0r + 9) * DHD + d] =
                        __floats2half2_rn(v2, v3);
                }
            } else {
                float b0v = bias[c], b1v = bias[c + 1];
                *(float2*)&out[(size_t)r0 * 512 + c]       = make_float2(v0 + b0v, v1 + b1v);
                *(float2*)&out[(size_t)(r0 + 8) * 512 + c] = make_float2(v2 + b0v, v3 + b1v);
            }
        }
    }
}

// ---------------------------------------------------------------------------
// Flash attention: scores in log2 domain, ex2.f16x2 softmax (MUFU halved),
// multiplicative half2 masking, register P, one bar/tile.
// ---------------------------------------------------------------------------
struct __align__(16) AttnSmemH {
    __half Qs[128][72];       // [q][d]
    __half Kt[2][64][72];     // [j][d]
    __half Vs[2][64][72];     // [j][d]
    __half kmh[2][64];        // key mask factors (1/0)
    __half kmh2[2][64];       // non-pad factors (1/0)
};

__device__ __forceinline__ void cp_kv_tile(AttnSmemH& s, int buf, const __half* Kb,
                                           const __half* Vb, int j0, int t) {
    #pragma unroll
    for (int i = 0; i < 2; i++) {
        int e = t + i * 256;
        int r = e >> 3, c8 = (e & 7) * 8;
        cpa16(&s.Kt[buf][r][c8], Kb + (size_t)(j0 + r) * DHD + c8);
        cpa16(&s.Vs[buf][r][c8], Vb + (size_t)(j0 + r) * DHD + c8);
    }
}

__global__ __launch_bounds__(256, 2) void attn_kernel(const unsigned int* __restrict__ qmask) {
    extern __shared__ char smem_raw[];
    AttnSmemH& s = *reinterpret_cast<AttnSmemH*>(smem_raw);

    int t = threadIdx.x, lane = t & 31, w = t >> 5;
    int n0 = blockIdx.x * QT;
    int h = blockIdx.y, b = blockIdx.z;
    int bh = b * HH + h;

    const __half* Qb = g_Qh + (size_t)bh * NN * DHD;
    const __half* Kb = g_Kh + (size_t)bh * MPAD * DHD;
    const __half* Vb = g_Vh + (size_t)bh * MPAD * DHD;
    const __half* km_base  = g_kmh  + b * MPAD;
    const __half* km2_base = g_kmh2 + b * MPAD;

    #pragma unroll
    for (int i = 0; i < 4; i++) {
        int e = t + i * 256;
        int q = e >> 3, c8 = (e & 7) * 8;
        *(uint4*)&s.Qs[q][c8] = *(const uint4*)&Qb[(size_t)(n0 + q) * DHD + c8];
    }
    cp_kv_tile(s, 0, Kb, Vb, 0, t);
    CP_COMMIT();
    if (t < 32) {
        ((uint32_t*)s.kmh[0])[t]  = ((const uint32_t*)km_base)[t];
        ((uint32_t*)s.kmh2[0])[t] = ((const uint32_t*)km2_base)[t];
    }
    CP_WAIT(0);
    __syncthreads();

    int g = lane >> 2, cl = lane & 3;
    int row_lo = w * 16 + g;
    int a_lr = lane & 15, a_lc = (lane >> 4) * 8;

    uint32_t aq[4][4];
    #pragma unroll
    for (int ko = 0; ko < 4; ko++)
        ldsm4(aq[ko], smem_u32(&s.Qs[w * 16 + a_lr][ko * 16 + a_lc]));

    int qml = (qmask[b * NN + n0 + row_lo]     != 0u) ? 1 : 0;
    int qmh = (qmask[b * NN + n0 + row_lo + 8] != 0u) ? 1 : 0;

    float l_lo = 0.f, l_hi = 0.f;
    float oacc[8][4] = {};
    int p = 0;

    int k_lr = (lane & 7) + 8 * (lane >> 4);
    int k_lc = 8 * ((lane >> 3) & 1);
    int v_lr = (lane & 7) + 8 * ((lane >> 3) & 1);
    int v_lc = 8 * (lane >> 4);

    for (int kt = 0; kt < NTILES; kt++) {
        if (kt < NTILES - 1) {
            int j1 = (kt + 1) * KT;
            cp_kv_tile(s, 1 - p, Kb, Vb, j1, t);
            CP_COMMIT();
            if (t < 32) {
                ((uint32_t*)s.kmh[1 - p])[t]  = ((const uint32_t*)(km_base  + j1))[t];
                ((uint32_t*)s.kmh2[1 - p])[t] = ((const uint32_t*)(km2_base + j1))[t];
            }
        }

        // ---- S' = Q K^T (log2-domain scores) ----
        float sacc[8][4] = {};
        #pragma unroll
        for (int ko = 0; ko < 4; ko++) {
            #pragma unroll
            for (int ntp = 0; ntp < 4; ntp++) {
                uint32_t bf[4];
                ldsm4(bf, smem_u32(&s.Kt[p][ntp * 16 + k_lr][ko * 16 + k_lc]));
                mma16(sacc[ntp * 2],     aq[ko], bf[0], bf[1]);
                mma16(sacc[ntp * 2 + 1], aq[ko], bf[2], bf[3]);
            }
        }

        // ---- softmax: p = ex2(s') * mask  (f16x2 MUFU, multiplicative mask) ----
        uint32_t pf_lo[8], pf_hi[8];
        #pragma unroll
        for (int nt = 0; nt < 8; nt++) {
            uint32_t m  = ((const uint32_t*)s.kmh[p])[nt * 4 + cl];
            uint32_t m2 = ((const uint32_t*)s.kmh2[p])[nt * 4 + cl];
            __half2 xlo = __floats2half2_rn(sacc[nt][0], sacc[nt][1]);
            __half2 xhi = __floats2half2_rn(sacc[nt][2], sacc[nt][3]);
            uint32_t elo = ex2_f16x2(*(uint32_t*)&xlo);
            uint32_t ehi = ex2_f16x2(*(uint32_t*)&xhi);
            __half2 plo = __hmul2(*(__half2*)&elo, *(__half2*)&m);
            __half2 phi = __hmul2(*(__half2*)&ehi, *(__half2*)&m);
            uint32_t plo_u = qml ? *(uint32_t*)&plo : m2;
            uint32_t phi_u = qmh ? *(uint32_t*)&phi : m2;
            float2 flo = __half22float2(*(__half2*)&plo_u);
            float2 fhi = __half22float2(*(__half2*)&phi_u);
            l_lo += flo.x + flo.y;
            l_hi += fhi.x + fhi.y;
            pf_lo[nt] = plo_u;
            pf_hi[nt] = phi_u;
        }

        // ---- O += P V from buffer p ----
        #pragma unroll
        for (int ko2 = 0; ko2 < 4; ko2++) {
            uint32_t pa[4] = { pf_lo[ko2 * 2], pf_hi[ko2 * 2],
                               pf_lo[ko2 * 2 + 1], pf_hi[ko2 * 2 + 1] };
            #pragma unroll
            for (int ntp = 0; ntp < 4; ntp++) {
                uint32_t bf[4];
                ldsm4t(bf, smem_u32(&s.Vs[p][ko2 * 16 + v_lr][ntp * 16 + v_lc]));
                mma16(oacc[ntp * 2],     pa, bf[0], bf[1]);
                mma16(oacc[ntp * 2 + 1], pa, bf[2], bf[3]);
            }
        }

        if (kt < NTILES - 1) {
            CP_WAIT(0);
            __syncthreads();
        }
        p ^= 1;
    }

    l_lo += __shfl_xor_sync(0xffffffffu, l_lo, 1);
    l_lo += __shfl_xor_sync(0xffffffffu, l_lo, 2);
    l_hi += __shfl_xor_sync(0xffffffffu, l_hi, 1);
    l_hi += __shfl_xor_sync(0xffffffffu, l_hi, 2);

    float li_lo = 1.f / l_lo, li_hi = 1.f / l_hi;
    #pragma unroll
    for (int nt = 0; nt < 8; nt++) {
        int c = nt * 8 + 2 * cl;
        size_t base_lo = ((size_t)b * NN + n0 + row_lo) * INNERD + h * DHD + c;
        size_t base_hi = ((size_t)b * NN + n0 + row_lo + 8) * INNERD + h * DHD + c;
        *(__half2*)&g_Oh[base_lo] = __floats2half2_rn(oacc[nt][0] * li_lo, oacc[nt][1] * li_lo);
        *(__half2*)&g_Oh[base_hi] = __floats2half2_rn(oacc[nt][2] * li_hi, oacc[nt][3] * li_hi);
    }
}

// ---------------------------------------------------------------------------
extern "C" void kernel_launch(void* const* d_in, const int* in_sizes, int n_in,
                              void* d_out, int out_size) {
    const float* x            = (const float*)d_in[0];
    const float* ctx          = (const float*)d_in[1];
    const unsigned int* mask  = (const unsigned int*)d_in[2];
    const unsigned int* cmask = (const unsigned int*)d_in[3];
    const float* Wq  = (const float*)d_in[4];
    const float* Wkv = (const float*)d_in[5];
    const float* Wo  = (const float*)d_in[6];
    const float* bo  = (const float*)d_in[7];
    const float* nk  = (const float*)d_in[8];
    const float* nv  = (const float*)d_in[9];
    float* out = (float*)d_out;

    static int inited = 0;
    if (!inited) {
        cudaFuncSetAttribute(attn_kernel, cudaFuncAttributeMaxDynamicSharedMemorySize,
                             (int)sizeof(AttnSmemH));
        inited = 1;
    }

    __half *oh, *woh;
    cudaGetSymbolAddress((void**)&oh,  g_Oh);
    cudaGetSymbolAddress((void**)&woh, g_woh);

    prep_all_kernel<<<NB_ROUND + NB_BIAS + NB_KV, 256>>>(x, ctx, Wq, Wkv, Wo, cmask, nk, nv);

    dim3 gqkv(12, 64);
    gemm_mma_h<<<gqkv, 256>>>(nullptr, nullptr, nullptr, nullptr, 0, 3);

    dim3 ga(NN / QT, HH, BB);                        // (16, 8, 4)
    attn_kernel<<<ga, 256, sizeof(AttnSmemH)>>>(mask);

    dim3 g2(512 / 128, (BB * NN) / 128);             // (4, 64)
    gemm_mma_h<<<g2, 256>>>(oh, woh, bo, out, 512, 2);
}

// round 14
// speedup vs baseline: 1.3439x; 1.0082x over previous
#include <cuda_runtime.h>
#include <cuda_fp16.h>
#include <math.h>
#include <stdint.h>

#define BB 4
#define NN 2048
#define MM 2048
#define HH 8
#define DHD 64
#define INNERD 512
#define MP 2049
#define MPAD 2176          // 34 * 64
#define KT 64
#define QT 128
#define NTILES (MPAD / KT) // 34
#define SCALEQ 0.18033688f // 0.125 * log2(e)

// Scratch (device globals; no allocation allowed)
__device__ __half g_Qh[(size_t)BB*HH*NN*DHD];    // [b,h,n,d]  tanh(q)*0.125*log2e
__device__ __half g_Kh[(size_t)BB*HH*MPAD*DHD];  // [b,h,j,d]  tanh(k), j=0 null, pad 0
__device__ __half g_Vh[(size_t)BB*HH*MPAD*DHD];  // [b,h,j,d]
__device__ __half g_Oh[(size_t)BB*NN*INNERD];    // [b,n,h*d]
__device__ __half g_kmh[BB*MPAD];                // 1 attendable / 0 masked / 0 pad
__device__ __half g_kmh2[BB*MPAD];               // 1 non-pad / 0 pad
__device__ __half g_xh[(size_t)BB*NN*512];
__device__ __half g_ch[(size_t)BB*MM*512];
__device__ __half g_wqh[512*512];
__device__ __half g_wkvh[512*1024];
__device__ __half g_woh[512*512];

__device__ __forceinline__ uint32_t smem_u32(const void* p) {
    return (uint32_t)__cvta_generic_to_shared(p);
}
__device__ __forceinline__ void ldsm4(uint32_t* r, uint32_t a) {
    asm volatile("ldmatrix.sync.aligned.m8n8.x4.shared.b16 {%0,%1,%2,%3}, [%4];"
        : "=r"(r[0]), "=r"(r[1]), "=r"(r[2]), "=r"(r[3]) : "r"(a));
}
__device__ __forceinline__ void ldsm4t(uint32_t* r, uint32_t a) {
    asm volatile("ldmatrix.sync.aligned.m8n8.x4.trans.shared.b16 {%0,%1,%2,%3}, [%4];"
        : "=r"(r[0]), "=r"(r[1]), "=r"(r[2]), "=r"(r[3]) : "r"(a));
}
__device__ __forceinline__ void mma16(float* d, const uint32_t* a, uint32_t b0, uint32_t b1) {
    asm volatile(
        "mma.sync.aligned.m16n8k16.row.col.f32.f16.f16.f32 "
        "{%0,%1,%2,%3}, {%4,%5,%6,%7}, {%8,%9}, {%0,%1,%2,%3};"
        : "+f"(d[0]), "+f"(d[1]), "+f"(d[2]), "+f"(d[3])
        : "r"(a[0]), "r"(a[1]), "r"(a[2]), "r"(a[3]), "r"(b0), "r"(b1));
}
__device__ __forceinline__ void cpa16(void* dst, const void* src) {
    uint32_t d = smem_u32(dst);
    asm volatile("cp.async.cg.shared.global [%0], [%1], 16;\n" :: "r"(d), "l"(src));
}
__device__ __forceinline__ uint32_t ex2_f16x2(uint32_t x) {
    uint32_t r;
    asm("ex2.approx.f16x2 %0, %1;" : "=r"(r) : "r"(x));
    return r;
}
#define CP_COMMIT() asm volatile("cp.async.commit_group;\n" ::: "memory")
#define CP_WAIT(n)  asm volatile("cp.async.wait_group %0;\n" :: "n"(n) : "memory")

// ---------------------------------------------------------------------------
// Fused prep (unchanged from R13)
// ---------------------------------------------------------------------------
#define N4_X   (BB*NN*512/4)
#define N4_C   (BB*MM*512/4)
#define N4_WQ  (512*512/4)
#define N4_WKV (512*1024/4)
#define N4_WO  (512*512/4)
#define N4_TOT (N4_X + N4_C + N4_WQ + N4_WKV + N4_WO)
#define NB_ROUND (N4_TOT / 1024)
#define NB_BIAS  ((BB * MPAD + 255) / 256)
#define NB_KV    (BB * HH)

__global__ void prep_all_kernel(const float* __restrict__ x, const float* __restrict__ ctx,
                                const float* __restrict__ wq, const float* __restrict__ wkv,
                                const float* __restrict__ wo,
                                const unsigned int* __restrict__ cmask,
                                const float* __restrict__ null_key,
                                const float* __restrict__ null_value) {
    int blk = blockIdx.x;
    if (blk < NB_ROUND) {
        int i0 = blk * 1024;
        const float* src; __half* dst; int seg0;
        if (i0 < N4_X)                               { src = x;   dst = g_xh;   seg0 = 0; }
        else if (i0 < N4_X + N4_C)                   { src = ctx; dst = g_ch;   seg0 = N4_X; }
        else if (i0 < N4_X + N4_C + N4_WQ)           { src = wq;  dst = g_wqh;  seg0 = N4_X + N4_C; }
        else if (i0 < N4_X + N4_C + N4_WQ + N4_WKV)  { src = wkv; dst = g_wkvh; seg0 = N4_X + N4_C + N4_WQ; }
        else                                         { src = wo;  dst = g_woh;  seg0 = N4_X + N4_C + N4_WQ + N4_WKV; }
        int off0 = i0 - seg0 + threadIdx.x;
        float4 v[4];
        #pragma unroll
        for (int j = 0; j < 4; j++)
            v[j] = ((const float4*)src)[off0 + j * 256];
        #pragma unroll
        for (int j = 0; j < 4; j++) {
            __half2 a = __floats2half2_rn(v[j].x, v[j].y);
            __half2 b = __floats2half2_rn(v[j].z, v[j].w);
            uint2 o;
            o.x = *(uint32_t*)&a;
            o.y = *(uint32_t*)&b;
            ((uint2*)dst)[off0 + j * 256] = o;
        }
    } else if (blk < NB_ROUND + NB_BIAS) {
        int t = (blk - NB_ROUND) * 256 + threadIdx.x;
        if (t >= BB * MPAD) return;
        int b = t / MPAD, j = t % MPAD;
        float m, m2;
        if (j == 0)        { m = 1.f; m2 = 1.f; }
        else if (j <= MM)  { m = (cmask[b * MM + (j - 1)] != 0u) ? 1.f : 0.f; m2 = 1.f; }
        else               { m = 0.f; m2 = 0.f; }
        g_kmh[t]  = __float2half_rn(m);
        g_kmh2[t] = __float2half_rn(m2);
    } else {
        int bh = blk - NB_ROUND - NB_BIAS;
        __half* Kb = g_Kh + (size_t)bh * MPAD * DHD;
        __half* Vb = g_Vh + (size_t)bh * MPAD * DHD;
        int t = threadIdx.x;
        if (t < DHD) {
            Kb[t] = __float2half_rn(tanhf(null_key[t]));
            Vb[t] = __float2half_rn(null_value[t]);
        }
        for (int idx = t; idx < DHD * (MPAD - MP); idx += 256) {
            int d = idx & 63, jr = idx >> 6;
            Kb[(size_t)(MP + jr) * DHD + d] = __float2half_rn(0.f);
            Vb[(size_t)(MP + jr) * DHD + d] = __float2half_rn(0.f);
        }
    }
}

// ---------------------------------------------------------------------------
// fp16 mma GEMM: k-chunk 32, THREE-stage cp.async ring (2 tiles in flight).
// mode 0: Q proj; 1: KV proj; 2: O proj; 3: fused Q+KV dispatch
// ---------------------------------------------------------------------------
__global__ __launch_bounds__(256, 2) void gemm_mma_h(
    const __half* __restrict__ A, const __half* __restrict__ W,
    const float* __restrict__ bias, float* __restrict__ out,
    int Ncols, int mode)
{
    __shared__ __align__(16) __half As[3][128][40];
    __shared__ __align__(16) __half Bs[3][32][136];

    int t = threadIdx.x, lane = t & 31, w = t >> 5;
    int wm = w >> 2, wn = w & 3;
    int g = lane >> 2, cl = lane & 3;
    int row0 = blockIdx.y * 128;
    int col0;
    if (mode == 3) {
        if (blockIdx.x < 4) { A = g_xh; W = g_wqh;  Ncols = 512;  mode = 0; col0 = blockIdx.x * 128; }
        else                { A = g_ch; W = g_wkvh; Ncols = 1024; mode = 1; col0 = (blockIdx.x - 4) * 128; }
    } else {
        col0 = blockIdx.x * 128;
    }

    int ar0 = t >> 2, ac = (t & 3) * 8;
    int br0 = t >> 4, bc = (t & 15) * 8;

    float acc[4][4][4] = {};

    // prologue: stage tiles 0, 1
    #pragma unroll
    for (int st = 0; st < 2; st++) {
        int k0 = st * 32;
        cpa16(&As[st][ar0][ac],      A + (size_t)(row0 + ar0) * 512 + k0 + ac);
        cpa16(&As[st][ar0 + 64][ac], A + (size_t)(row0 + ar0 + 64) * 512 + k0 + ac);
        cpa16(&Bs[st][br0][bc],      W + (size_t)(k0 + br0) * Ncols + col0 + bc);
        cpa16(&Bs[st][br0 + 16][bc], W + (size_t)(k0 + br0 + 16) * Ncols + col0 + bc);
        CP_COMMIT();
    }

    int a_lr = lane & 15, a_lc = (lane >> 4) * 8;
    int b_lr = (lane & 7) + 8 * ((lane >> 3) & 1), b_lc = 8 * (lane >> 4);

    int cur = 0;
    for (int kt = 0; kt < 16; kt++) {
        if (kt == 15) { CP_WAIT(0); } else { CP_WAIT(1); }
        __syncthreads();

        if (kt < 14) {
            int nb = cur + 2; if (nb >= 3) nb -= 3;
            int k0 = (kt + 2) * 32;
            cpa16(&As[nb][ar0][ac],      A + (size_t)(row0 + ar0) * 512 + k0 + ac);
            cpa16(&As[nb][ar0 + 64][ac], A + (size_t)(row0 + ar0 + 64) * 512 + k0 + ac);
            cpa16(&Bs[nb][br0][bc],      W + (size_t)(k0 + br0) * Ncols + col0 + bc);
            cpa16(&Bs[nb][br0 + 16][bc], W + (size_t)(k0 + br0 + 16) * Ncols + col0 + bc);
            CP_COMMIT();
        }

        #pragma unroll
        for (int kc = 0; kc < 2; kc++) {
            uint32_t af[4][4];
            #pragma unroll
            for (int mi = 0; mi < 4; mi++)
                ldsm4(af[mi], smem_u32(&As[cur][wm * 64 + mi * 16 + a_lr][kc * 16 + a_lc]));
            #pragma unroll
            for (int np = 0; np < 2; np++) {
                uint32_t bf[4];
                ldsm4t(bf, smem_u32(&Bs[cur][kc * 16 + b_lr][wn * 32 + np * 16 + b_lc]));
                #pragma unroll
                for (int mi = 0; mi < 4; mi++) {
                    mma16(acc[mi][np * 2],     af[mi], bf[0], bf[1]);
                    mma16(acc[mi][np * 2 + 1], af[mi], bf[2], bf[3]);
                }
            }
        }
        cur = cur + 1; if (cur >= 3) cur -= 3;
    }

    int bidx = row0 >> 11;
    #pragma unroll
    for (int mi = 0; mi < 4; mi++) {
        int r0 = row0 + wm * 64 + mi * 16 + g;
        int n0r = r0 & 2047;
        #pragma unroll
        for (int ni = 0; ni < 4; ni++) {
            int c = col0 + wn * 32 + ni * 8 + 2 * cl;
            float v0 = acc[mi][ni][0], v1 = acc[mi][ni][1];
            float v2 = acc[mi][ni][2], v3 = acc[mi][ni][3];
            if (mode == 0) {
                int hh = c >> 6, d = c & 63;
                *(__half2*)&g_Qh[(((size_t)bidx * HH + hh) * NN + n0r) * DHD + d] =
                    __floats2half2_rn(tanhf(v0) * SCALEQ, tanhf(v1) * SCALEQ);
                *(__half2*)&g_Qh[(((size_t)bidx * HH + hh) * NN + n0r + 8) * DHD + d] =
                    __floats2half2_rn(tanhf(v2) * SCALEQ, tanhf(v3) * SCALEQ);
            } else if (mode == 1) {
                if (c < INNERD) {
                    int hh = c >> 6, d = c & 63;
                    *(__half2*)&g_Kh[(((size_t)bidx * HH + hh) * MPAD + n0r + 1) * DHD + d] =
                        __floats2half2_rn(tanhf(v0), tanhf(v1));
                    *(__half2*)&g_Kh[(((size_t)bidx * HH + hh) * MPAD + n0r + 9) * DHD + d] =
                        __floats2half2_rn(tanhf(v2), tanhf(v3));
                } else {
                    int c2 = c - INNERD;
                    int hh = c2 >> 6, d = c2 & 63;
                    *(__half2*)&g_Vh[(((size_t)bidx * HH + hh) * MPAD + n0r + 1) * DHD + d] =
                        __floats2half2_rn(v0, v1);
                    *(__half2*)&g_Vh[(((size_t)bidx * HH + hh) * MPAD + n0r + 9) * DHD + d] =
                        __floats2half2_rn(v2, v3);
                }
            } else {
                float b0v = bias[c], b1v = bias[c + 1];
                *(float2*)&out[(size_t)r0 * 512 + c]       = make_float2(v0 + b0v, v1 + b1v);
                *(float2*)&out[(size_t)(r0 + 8) * 512 + c] = make_float2(v2 + b0v, v3 + b1v);
            }
        }
    }
}

// ---------------------------------------------------------------------------
// Flash attention: log2-domain ex2.f16x2 softmax, register P,
// THREE-stage cp.async ring for K/V/masks.
// ---------------------------------------------------------------------------
struct __align__(16) AttnSmemH {
    __half Qs[128][72];       // [q][d]
    __half Kt[3][64][72];     // [j][d]
    __half Vs[3][64][72];     // [j][d]
    __half kmh[3][64];
    __half kmh2[3][64];
};

__device__ __forceinline__ void cp_kv_tile(AttnSmemH& s, int buf, const __half* Kb,
                                           const __half* Vb, int j0, int t) {
    #pragma unroll
    for (int i = 0; i < 2; i++) {
        int e = t + i * 256;
        int r = e >> 3, c8 = (e & 7) * 8;
        cpa16(&s.Kt[buf][r][c8], Kb + (size_t)(j0 + r) * DHD + c8);
        cpa16(&s.Vs[buf][r][c8], Vb + (size_t)(j0 + r) * DHD + c8);
    }
}

__global__ __launch_bounds__(256, 2) void attn_kernel(const unsigned int* __restrict__ qmask) {
    extern __shared__ char smem_raw[];
    AttnSmemH& s = *reinterpret_cast<AttnSmemH*>(smem_raw);

    int t = threadIdx.x, lane = t & 31, w = t >> 5;
    int n0 = blockIdx.x * QT;
    int h = blockIdx.y, b = blockIdx.z;
    int bh = b * HH + h;

    const __half* Qb = g_Qh + (size_t)bh * NN * DHD;
    const __half* Kb = g_Kh + (size_t)bh * MPAD * DHD;
    const __half* Vb = g_Vh + (size_t)bh * MPAD * DHD;
    const __half* km_base  = g_kmh  + b * MPAD;
    const __half* km2_base = g_kmh2 + b * MPAD;

    #pragma unroll
    for (int i = 0; i < 4; i++) {
        int e = t + i * 256;
        int q = e >> 3, c8 = (e & 7) * 8;
        *(uint4*)&s.Qs[q][c8] = *(const uint4*)&Qb[(size_t)(n0 + q) * DHD + c8];
    }
    // prologue: tiles 0, 1
    #pragma unroll
    for (int st = 0; st < 2; st++) {
        cp_kv_tile(s, st, Kb, Vb, st * KT, t);
        CP_COMMIT();
        if (t < 32) {
            ((uint32_t*)s.kmh[st])[t]  = ((const uint32_t*)(km_base  + st * KT))[t];
            ((uint32_t*)s.kmh2[st])[t] = ((const uint32_t*)(km2_base + st * KT))[t];
        }
    }
    __syncthreads();   // Qs ready for ldmatrix

    int g = lane >> 2, cl = lane & 3;
    int row_lo = w * 16 + g;
    int a_lr = lane & 15, a_lc = (lane >> 4) * 8;

    uint32_t aq[4][4];
    #pragma unroll
    for (int ko = 0; ko < 4; ko++)
        ldsm4(aq[ko], smem_u32(&s.Qs[w * 16 + a_lr][ko * 16 + a_lc]));

    int qml = (qmask[b * NN + n0 + row_lo]     != 0u) ? 1 : 0;
    int qmh = (qmask[b * NN + n0 + row_lo + 8] != 0u) ? 1 : 0;

    float l_lo = 0.f, l_hi = 0.f;
    float oacc[8][4] = {};
    int cur = 0;

    int k_lr = (lane & 7) + 8 * (lane >> 4);
    int k_lc = 8 * ((lane >> 3) & 1);
    int v_lr = (lane & 7) + 8 * ((lane >> 3) & 1);
    int v_lc = 8 * (lane >> 4);

    for (int kt = 0; kt < NTILES; kt++) {
        if (kt == NTILES - 1) { CP_WAIT(0); } else { CP_WAIT(1); }
        __syncthreads();

        if (kt < NTILES - 2) {
            int nb = cur + 2; if (nb >= 3) nb -= 3;
            int j1 = (kt + 2) * KT;
            cp_kv_tile(s, nb, Kb, Vb, j1, t);
            CP_COMMIT();
            if (t < 32) {
                ((uint32_t*)s.kmh[nb])[t]  = ((const uint32_t*)(km_base  + j1))[t];
                ((uint32_t*)s.kmh2[nb])[t] = ((const uint32_t*)(km2_base + j1))[t];
            }
        }

        // ---- S' = Q K^T (log2-domain scores) ----
        float sacc[8][4] = {};
        #pragma unroll
        for (int ko = 0; ko < 4; ko++) {
            #pragma unroll
            for (int ntp = 0; ntp < 4; ntp++) {
                uint32_t bf[4];
                ldsm4(bf, smem_u32(&s.Kt[cur][ntp * 16 + k_lr][ko * 16 + k_lc]));
                mma16(sacc[ntp * 2],     aq[ko], bf[0], bf[1]);
                mma16(sacc[ntp * 2 + 1], aq[ko], bf[2], bf[3]);
            }
        }

        // ---- softmax: p = ex2(s') * mask ----
        uint32_t pf_lo[8], pf_hi[8];
        #pragma unroll
        for (int nt = 0; nt < 8; nt++) {
            uint32_t m  = ((const uint32_t*)s.kmh[cur])[nt * 4 + cl];
            uint32_t m2 = ((const uint32_t*)s.kmh2[cur])[nt * 4 + cl];
            __half2 xlo = __floats2half2_rn(sacc[nt][0], sacc[nt][1]);
            __half2 xhi = __floats2half2_rn(sacc[nt][2], sacc[nt][3]);
            uint32_t elo = ex2_f16x2(*(uint32_t*)&xlo);
            uint32_t ehi = ex2_f16x2(*(uint32_t*)&xhi);
            __half2 plo = __hmul2(*(__half2*)&elo, *(__half2*)&m);
            __half2 phi = __hmul2(*(__half2*)&ehi, *(__half2*)&m);
            uint32_t plo_u = qml ? *(uint32_t*)&plo : m2;
            uint32_t phi_u = qmh ? *(uint32_t*)&phi : m2;
            float2 flo = __half22float2(*(__half2*)&plo_u);
            float2 fhi = __half22float2(*(__half2*)&phi_u);
            l_lo += flo.x + flo.y;
            l_hi += fhi.x + fhi.y;
            pf_lo[nt] = plo_u;
            pf_hi[nt] = phi_u;
        }

        // ---- O += P V ----
        #pragma unroll
        for (int ko2 = 0; ko2 < 4; ko2++) {
            uint32_t pa[4] = { pf_lo[ko2 * 2], pf_hi[ko2 * 2],
                               pf_lo[ko2 * 2 + 1], pf_hi[ko2 * 2 + 1] };
            #pragma unroll
            for (int ntp = 0; ntp < 4; ntp++) {
                uint32_t bf[4];
                ldsm4t(bf, smem_u32(&s.Vs[cur][ko2 * 16 + v_lr][ntp * 16 + v_lc]));
                mma16(oacc[ntp * 2],     pa, bf[0], bf[1]);
                mma16(oacc[ntp * 2 + 1], pa, bf[2], bf[3]);
            }
        }
        cur = cur + 1; if (cur >= 3) cur -= 3;
    }

    l_lo += __shfl_xor_sync(0xffffffffu, l_lo, 1);
    l_lo += __shfl_xor_sync(0xffffffffu, l_lo, 2);
    l_hi += __shfl_xor_sync(0xffffffffu, l_hi, 1);
    l_hi += __shfl_xor_sync(0xffffffffu, l_hi, 2);

    float li_lo = 1.f / l_lo, li_hi = 1.f / l_hi;
    #pragma unroll
    for (int nt = 0; nt < 8; nt++) {
        int c = nt * 8 + 2 * cl;
        size_t base_lo = ((size_t)b * NN + n0 + row_lo) * INNERD + h * DHD + c;
        size_t base_hi = ((size_t)b * NN + n0 + row_lo + 8) * INNERD + h * DHD + c;
        *(__half2*)&g_Oh[base_lo] = __floats2half2_rn(oacc[nt][0] * li_lo, oacc[nt][1] * li_lo);
        *(__half2*)&g_Oh[base_hi] = __floats2half2_rn(oacc[nt][2] * li_hi, oacc[nt][3] * li_hi);
    }
}

// ---------------------------------------------------------------------------
extern "C" void kernel_launch(void* const* d_in, const int* in_sizes, int n_in,
                              void* d_out, int out_size) {
    const float* x            = (const float*)d_in[0];
    const float* ctx          = (const float*)d_in[1];
    const unsigned int* mask  = (const unsigned int*)d_in[2];
    const unsigned int* cmask = (const unsigned int*)d_in[3];
    const float* Wq  = (const float*)d_in[4];
    const float* Wkv = (const float*)d_in[5];
    const float* Wo  = (const float*)d_in[6];
    const float* bo  = (const float*)d_in[7];
    const float* nk  = (const float*)d_in[8];
    const float* nv  = (const float*)d_in[9];
    float* out = (float*)d_out;

    static int inited = 0;
    if (!inited) {
        cudaFuncSetAttribute(attn_kernel, cudaFuncAttributeMaxDynamicSharedMemorySize,
                             (int)sizeof(AttnSmemH));
        inited = 1;
    }

    __half *oh, *woh;
    cudaGetSymbolAddress((void**)&oh,  g_Oh);
    cudaGetSymbolAddress((void**)&woh, g_woh);

    prep_all_kernel<<<NB_ROUND + NB_BIAS + NB_KV, 256>>>(x, ctx, Wq, Wkv, Wo, cmask, nk, nv);

    dim3 gqkv(12, 64);
    gemm_mma_h<<<gqkv, 256>>>(nullptr, nullptr, nullptr, nullptr, 0, 3);

    dim3 ga(NN / QT, HH, BB);                        // (16, 8, 4)
    attn_kernel<<<ga, 256, sizeof(AttnSmemH)>>>(mask);

    dim3 g2(512 / 128, (BB * NN) / 128);             // (4, 64)
    gemm_mma_h<<<g2, 256>>>(oh, woh, bo, out, 512, 2);
}

// round 16
// speedup vs baseline: 1.3857x; 1.0312x over previous
#include <cuda_runtime.h>
#include <cuda_fp16.h>
#include <math.h>
#include <stdint.h>

#define BB 4
#define NN 2048
#define MM 2048
#define HH 8
#define DHD 64
#define INNERD 512
#define MP 2049
#define MPAD 2112          // 33 * 64 (last tile: j=2048 real, rest pad)
#define KT 64
#define QT 128
#define NTILES (MPAD / KT) // 33
#define SCALEQ 0.18033688f // 0.125 * log2(e)

// Scratch (device globals; no allocation allowed)
__device__ __half g_Qh[(size_t)BB*HH*NN*DHD];    // [b,h,n,d]  tanh(q)*0.125*log2e
__device__ __half g_Kh[(size_t)BB*HH*MPAD*DHD];  // [b,h,j,d]  tanh(k), j=0 null, pad 0
__device__ __half g_Vh[(size_t)BB*HH*MPAD*DHD];  // [b,h,j,d]
__device__ __half g_Oh[(size_t)BB*NN*INNERD];    // [b,n,h*d]
__device__ __half g_kmh[BB*MPAD];                // 1 attendable / 0 masked / 0 pad
__device__ __half g_kmh2[BB*MPAD];               // 1 non-pad / 0 pad
__device__ __half g_xh[(size_t)BB*NN*512];
__device__ __half g_ch[(size_t)BB*MM*512];
__device__ __half g_wqh[512*512];
__device__ __half g_wkvh[512*1024];
__device__ __half g_woh[512*512];

__device__ __forceinline__ uint32_t smem_u32(const void* p) {
    return (uint32_t)__cvta_generic_to_shared(p);
}
__device__ __forceinline__ void ldsm4(uint32_t* r, uint32_t a) {
    asm volatile("ldmatrix.sync.aligned.m8n8.x4.shared.b16 {%0,%1,%2,%3}, [%4];"
        : "=r"(r[0]), "=r"(r[1]), "=r"(r[2]), "=r"(r[3]) : "r"(a));
}
__device__ __forceinline__ void ldsm4t(uint32_t* r, uint32_t a) {
    asm volatile("ldmatrix.sync.aligned.m8n8.x4.trans.shared.b16 {%0,%1,%2,%3}, [%4];"
        : "=r"(r[0]), "=r"(r[1]), "=r"(r[2]), "=r"(r[3]) : "r"(a));
}
__device__ __forceinline__ void mma16(float* d, const uint32_t* a, uint32_t b0, uint32_t b1) {
    asm volatile(
        "mma.sync.aligned.m16n8k16.row.col.f32.f16.f16.f32 "
        "{%0,%1,%2,%3}, {%4,%5,%6,%7}, {%8,%9}, {%0,%1,%2,%3};"
        : "+f"(d[0]), "+f"(d[1]), "+f"(d[2]), "+f"(d[3])
        : "r"(a[0]), "r"(a[1]), "r"(a[2]), "r"(a[3]), "r"(b0), "r"(b1));
}
// fp16-accumulator variant: d[0]=(row g, 2 cols), d[1]=(row g+8, 2 cols)
__device__ __forceinline__ void mma16h(uint32_t* d, const uint32_t* a, uint32_t b0, uint32_t b1) {
    asm volatile(
        "mma.sync.aligned.m16n8k16.row.col.f16.f16.f16.f16 "
        "{%0,%1}, {%2,%3,%4,%5}, {%6,%7}, {%0,%1};"
        : "+r"(d[0]), "+r"(d[1])
        : "r"(a[0]), "r"(a[1]), "r"(a[2]), "r"(a[3]), "r"(b0), "r"(b1));
}
__device__ __forceinline__ void cpa16(void* dst, const void* src) {
    uint32_t d = smem_u32(dst);
    asm volatile("cp.async.cg.shared.global [%0], [%1], 16;\n" :: "r"(d), "l"(src));
}
__device__ __forceinline__ uint32_t ex2_f16x2(uint32_t x) {
    uint32_t r;
    asm("ex2.approx.f16x2 %0, %1;" : "=r"(r) : "r"(x));
    return r;
}
#define CP_COMMIT() asm volatile("cp.async.commit_group;\n" ::: "memory")
#define CP_WAIT(n)  asm volatile("cp.async.wait_group %0;\n" :: "n"(n) : "memory")

// ---------------------------------------------------------------------------
// Fused prep: fp32->fp16 rounding + mask tables + null/pad KV
// ---------------------------------------------------------------------------
#define N4_X   (BB*NN*512/4)
#define N4_C   (BB*MM*512/4)
#define N4_WQ  (512*512/4)
#define N4_WKV (512*1024/4)
#define N4_WO  (512*512/4)
#define N4_TOT (N4_X + N4_C + N4_WQ + N4_WKV + N4_WO)
#define NB_ROUND (N4_TOT / 1024)
#define NB_BIAS  ((BB * MPAD + 255) / 256)
#define NB_KV    (BB * HH)

__global__ void prep_all_kernel(const float* __restrict__ x, const float* __restrict__ ctx,
                                const float* __restrict__ wq, const float* __restrict__ wkv,
                                const float* __restrict__ wo,
                                const unsigned int* __restrict__ cmask,
                                const float* __restrict__ null_key,
                                const float* __restrict__ null_value) {
    int blk = blockIdx.x;
    if (blk < NB_ROUND) {
        int i0 = blk * 1024;
        const float* src; __half* dst; int seg0;
        if (i0 < N4_X)                               { src = x;   dst = g_xh;   seg0 = 0; }
        else if (i0 < N4_X + N4_C)                   { src = ctx; dst = g_ch;   seg0 = N4_X; }
        else if (i0 < N4_X + N4_C + N4_WQ)           { src = wq;  dst = g_wqh;  seg0 = N4_X + N4_C; }
        else if (i0 < N4_X + N4_C + N4_WQ + N4_WKV)  { src = wkv; dst = g_wkvh; seg0 = N4_X + N4_C + N4_WQ; }
        else                                         { src = wo;  dst = g_woh;  seg0 = N4_X + N4_C + N4_WQ + N4_WKV; }
        int off0 = i0 - seg0 + threadIdx.x;
        float4 v[4];
        #pragma unroll
        for (int j = 0; j < 4; j++)
            v[j] = ((const float4*)src)[off0 + j * 256];
        #pragma unroll
        for (int j = 0; j < 4; j++) {
            __half2 a = __floats2half2_rn(v[j].x, v[j].y);
            __half2 b = __floats2half2_rn(v[j].z, v[j].w);
            uint2 o; o.x = *(uint32_t*)&a; o.y = *(uint32_t*)&b;
            ((uint2*)dst)[off0 + j * 256] = o;
        }
    } else if (blk < NB_ROUND + NB_BIAS) {
        int t = (blk - NB_ROUND) * 256 + threadIdx.x;
        if (t >= BB * MPAD) return;
        int b = t / MPAD, j = t % MPAD;
        float m, m2;
        if (j == 0)        { m = 1.f; m2 = 1.f; }
        else if (j <= MM)  { m = (cmask[b * MM + (j - 1)] != 0u) ? 1.f : 0.f; m2 = 1.f; }
        else               { m = 0.f; m2 = 0.f; }
        g_kmh[t]  = __float2half_rn(m);
        g_kmh2[t] = __float2half_rn(m2);
    } else {
        int bh = blk - NB_ROUND - NB_BIAS;
        __half* Kb = g_Kh + (size_t)bh * MPAD * DHD;
        __half* Vb = g_Vh + (size_t)bh * MPAD * DHD;
        int t = threadIdx.x;
        if (t < DHD) {
            Kb[t] = __float2half_rn(tanhf(null_key[t]));
            Vb[t] = __float2half_rn(null_value[t]);
        }
        for (int idx = t; idx < DHD * (MPAD - MP); idx += 256) {
            int d = idx & 63, jr = idx >> 6;
            Kb[(size_t)(MP + jr) * DHD + d] = __float2half_rn(0.f);
            Vb[(size_t)(MP + jr) * DHD + d] = __float2half_rn(0.f);
        }
    }
}

// ---------------------------------------------------------------------------
// fp16 mma GEMM: k-chunk 32, 3-stage cp.async ring (R14 version)
// mode 0: Q proj; 1: KV proj; 2: O proj; 3: fused Q+KV dispatch
// ---------------------------------------------------------------------------
__global__ __launch_bounds__(256, 2) void gemm_mma_h(
    const __half* __restrict__ A, const __half* __restrict__ W,
    const float* __restrict__ bias, float* __restrict__ out,
    int Ncols, int mode)
{
    __shared__ __align__(16) __half As[3][128][40];
    __shared__ __align__(16) __half Bs[3][32][136];

    int t = threadIdx.x, lane = t & 31, w = t >> 5;
    int wm = w >> 2, wn = w & 3;
    int g = lane >> 2, cl = lane & 3;
    int row0 = blockIdx.y * 128;
    int col0;
    if (mode == 3) {
        if (blockIdx.x < 4) { A = g_xh; W = g_wqh;  Ncols = 512;  mode = 0; col0 = blockIdx.x * 128; }
        else                { A = g_ch; W = g_wkvh; Ncols = 1024; mode = 1; col0 = (blockIdx.x - 4) * 128; }
    } else {
        col0 = blockIdx.x * 128;
    }

    int ar0 = t >> 2, ac = (t & 3) * 8;
    int br0 = t >> 4, bc = (t & 15) * 8;

    float acc[4][4][4] = {};

    #pragma unroll
    for (int st = 0; st < 2; st++) {
        int k0 = st * 32;
        cpa16(&As[st][ar0][ac],      A + (size_t)(row0 + ar0) * 512 + k0 + ac);
        cpa16(&As[st][ar0 + 64][ac], A + (size_t)(row0 + ar0 + 64) * 512 + k0 + ac);
        cpa16(&Bs[st][br0][bc],      W + (size_t)(k0 + br0) * Ncols + col0 + bc);
        cpa16(&Bs[st][br0 + 16][bc], W + (size_t)(k0 + br0 + 16) * Ncols + col0 + bc);
        CP_COMMIT();
    }

    int a_lr = lane & 15, a_lc = (lane >> 4) * 8;
    int b_lr = (lane & 7) + 8 * ((lane >> 3) & 1), b_lc = 8 * (lane >> 4);

    int cur = 0;
    for (int kt = 0; kt < 16; kt++) {
        if (kt == 15) { CP_WAIT(0); } else { CP_WAIT(1); }
        __syncthreads();

        if (kt < 14) {
            int nb = cur + 2; if (nb >= 3) nb -= 3;
            int k0 = (kt + 2) * 32;
            cpa16(&As[nb][ar0][ac],      A + (size_t)(row0 + ar0) * 512 + k0 + ac);
            cpa16(&As[nb][ar0 + 64][ac], A + (size_t)(row0 + ar0 + 64) * 512 + k0 + ac);
            cpa16(&Bs[nb][br0][bc],      W + (size_t)(k0 + br0) * Ncols + col0 + bc);
            cpa16(&Bs[nb][br0 + 16][bc], W + (size_t)(k0 + br0 + 16) * Ncols + col0 + bc);
            CP_COMMIT();
        }

        #pragma unroll
        for (int kc = 0; kc < 2; kc++) {
            uint32_t af[4][4];
            #pragma unroll
            for (int mi = 0; mi < 4; mi++)
                ldsm4(af[mi], smem_u32(&As[cur][wm * 64 + mi * 16 + a_lr][kc * 16 + a_lc]));
            #pragma unroll
            for (int np = 0; np < 2; np++) {
                uint32_t bf[4];
                ldsm4t(bf, smem_u32(&Bs[cur][kc * 16 + b_lr][wn * 32 + np * 16 + b_lc]));
                #pragma unroll
                for (int mi = 0; mi < 4; mi++) {
                    mma16(acc[mi][np * 2],     af[mi], bf[0], bf[1]);
                    mma16(acc[mi][np * 2 + 1], af[mi], bf[2], bf[3]);
                }
            }
        }
        cur = cur + 1; if (cur >= 3) cur -= 3;
    }

    int bidx = row0 >> 11;
    #pragma unroll
    for (int mi = 0; mi < 4; mi++) {
        int r0 = row0 + wm * 64 + mi * 16 + g;
        int n0r = r0 & 2047;
        #pragma unroll
        for (int ni = 0; ni < 4; ni++) {
            int c = col0 + wn * 32 + ni * 8 + 2 * cl;
            float v0 = acc[mi][ni][0], v1 = acc[mi][ni][1];
            float v2 = acc[mi][ni][2], v3 = acc[mi][ni][3];
            if (mode == 0) {
                int hh = c >> 6, d = c & 63;
                *(__half2*)&g_Qh[(((size_t)bidx * HH + hh) * NN + n0r) * DHD + d] =
                    __floats2half2_rn(tanhf(v0) * SCALEQ, tanhf(v1) * SCALEQ);
                *(__half2*)&g_Qh[(((size_t)bidx * HH + hh) * NN + n0r + 8) * DHD + d] =
                    __floats2half2_rn(tanhf(v2) * SCALEQ, tanhf(v3) * SCALEQ);
            } else if (mode == 1) {
                if (c < INNERD) {
                    int hh = c >> 6, d = c & 63;
                    *(__half2*)&g_Kh[(((size_t)bidx * HH + hh) * MPAD + n0r + 1) * DHD + d] =
                        __floats2half2_rn(tanhf(v0), tanhf(v1));
                    *(__half2*)&g_Kh[(((size_t)bidx * HH + hh) * MPAD + n0r + 9) * DHD + d] =
                        __floats2half2_rn(tanhf(v2), tanhf(v3));
                } else {
                    int c2 = c - INNERD;
                    int hh = c2 >> 6, d = c2 & 63;
                    *(__half2*)&g_Vh[(((size_t)bidx * HH + hh) * MPAD + n0r + 1) * DHD + d] =
                        __floats2half2_rn(v0, v1);
                    *(__half2*)&g_Vh[(((size_t)bidx * HH + hh) * MPAD + n0r + 9) * DHD + d] =
                        __floats2half2_rn(v2, v3);
                }
            } else {
                float b0v = bias[c], b1v = bias[c + 1];
                *(float2*)&out[(size_t)r0 * 512 + c]       = make_float2(v0 + b0v, v1 + b1v);
                *(float2*)&out[(size_t)(r0 + 8) * 512 + c] = make_float2(v2 + b0v, v3 + b1v);
            }
        }
    }
}

// ---------------------------------------------------------------------------
// Flash attention: log2-domain scores with fp16 mma accumulators (C-frag is
// pre-packed half2 pairs -> ex2.f16x2 + mask multiply with zero cvt overhead),
// register P, fp32 PV accumulation, 3-stage cp.async ring.
// ---------------------------------------------------------------------------
struct __align__(16) AttnSmemH {
    __half Qs[128][72];
    __half Kt[3][64][72];
    __half Vs[3][64][72];
    __half kmh[3][64];
    __half kmh2[3][64];
};

__device__ __forceinline__ void cp_kv_tile(AttnSmemH& s, int buf, const __half* Kb,
                                           const __half* Vb, int j0, int t) {
    #pragma unroll
    for (int i = 0; i < 2; i++) {
        int e = t + i * 256;
        int r = e >> 3, c8 = (e & 7) * 8;
        cpa16(&s.Kt[buf][r][c8], Kb + (size_t)(j0 + r) * DHD + c8);
        cpa16(&s.Vs[buf][r][c8], Vb + (size_t)(j0 + r) * DHD + c8);
    }
}

__global__ __launch_bounds__(256, 2) void attn_kernel(const unsigned int* __restrict__ qmask) {
    extern __shared__ char smem_raw[];
    AttnSmemH& s = *reinterpret_cast<AttnSmemH*>(smem_raw);

    int t = threadIdx.x, lane = t & 31, w = t >> 5;
    int n0 = blockIdx.x * QT;
    int h = blockIdx.y, b = blockIdx.z;
    int bh = b * HH + h;

    const __half* Qb = g_Qh + (size_t)bh * NN * DHD;
    const __half* Kb = g_Kh + (size_t)bh * MPAD * DHD;
    const __half* Vb = g_Vh + (size_t)bh * MPAD * DHD;
    const __half* km_base  = g_kmh  + b * MPAD;
    const __half* km2_base = g_kmh2 + b * MPAD;

    #pragma unroll
    for (int i = 0; i < 4; i++) {
        int e = t + i * 256;
        int q = e >> 3, c8 = (e & 7) * 8;
        *(uint4*)&s.Qs[q][c8] = *(const uint4*)&Qb[(size_t)(n0 + q) * DHD + c8];
    }
    #pragma unroll
    for (int st = 0; st < 2; st++) {
        cp_kv_tile(s, st, Kb, Vb, st * KT, t);
        CP_COMMIT();
        if (t < 32) {
            ((uint32_t*)s.kmh[st])[t]  = ((const uint32_t*)(km_base  + st * KT))[t];
            ((uint32_t*)s.kmh2[st])[t] = ((const uint32_t*)(km2_base + st * KT))[t];
        }
    }
    __syncthreads();

    int g = lane >> 2, cl = lane & 3;
    int row_lo = w * 16 + g;
    int a_lr = lane & 15, a_lc = (lane >> 4) * 8;

    uint32_t aq[4][4];
    #pragma unroll
    for (int ko = 0; ko < 4; ko++)
        ldsm4(aq[ko], smem_u32(&s.Qs[w * 16 + a_lr][ko * 16 + a_lc]));

    int qml = (qmask[b * NN + n0 + row_lo]     != 0u) ? 1 : 0;
    int qmh = (qmask[b * NN + n0 + row_lo + 8] != 0u) ? 1 : 0;

    float l_lo = 0.f, l_hi = 0.f;
    float oacc[8][4] = {};
    int cur = 0;

    int k_lr = (lane & 7) + 8 * (lane >> 4);
    int k_lc = 8 * ((lane >> 3) & 1);
    int v_lr = (lane & 7) + 8 * ((lane >> 3) & 1);
    int v_lc = 8 * (lane >> 4);

    for (int kt = 0; kt < NTILES; kt++) {
        if (kt == NTILES - 1) { CP_WAIT(0); } else { CP_WAIT(1); }
        __syncthreads();

        if (kt < NTILES - 2) {
            int nb = cur + 2; if (nb >= 3) nb -= 3;
            int j1 = (kt + 2) * KT;
            cp_kv_tile(s, nb, Kb, Vb, j1, t);
            CP_COMMIT();
            if (t < 32) {
                ((uint32_t*)s.kmh[nb])[t]  = ((const uint32_t*)(km_base  + j1))[t];
                ((uint32_t*)s.kmh2[nb])[t] = ((const uint32_t*)(km2_base + j1))[t];
            }
        }

        // ---- S' = Q K^T (log2 domain), fp16 accumulators ----
        uint32_t sacc[8][2] = {};
        #pragma unroll
        for (int ko = 0; ko < 4; ko++) {
            #pragma unroll
            for (int ntp = 0; ntp < 4; ntp++) {
                uint32_t bf[4];
                ldsm4(bf, smem_u32(&s.Kt[cur][ntp * 16 + k_lr][ko * 16 + k_lc]));
                mma16h(sacc[ntp * 2],     aq[ko], bf[0], bf[1]);
                mma16h(sacc[ntp * 2 + 1], aq[ko], bf[2], bf[3]);
            }
        }

        // ---- softmax: p = ex2(s') * mask (all in packed f16x2) ----
        uint32_t pf_lo[8], pf_hi[8];
        #pragma unroll
        for (int nt = 0; nt < 8; nt++) {
            uint32_t m  = ((const uint32_t*)s.kmh[cur])[nt * 4 + cl];
            uint32_t m2 = ((const uint32_t*)s.kmh2[cur])[nt * 4 + cl];
            uint32_t elo = ex2_f16x2(sacc[nt][0]);
            uint32_t ehi = ex2_f16x2(sacc[nt][1]);
            __half2 plo = __hmul2(*(__half2*)&elo, *(__half2*)&m);
            __half2 phi = __hmul2(*(__half2*)&ehi, *(__half2*)&m);
            uint32_t plo_u = qml ? *(uint32_t*)&plo : m2;
            uint32_t phi_u = qmh ? *(uint32_t*)&phi : m2;
            float2 flo = __half22float2(*(__half2*)&plo_u);
            float2 fhi = __half22float2(*(__half2*)&phi_u);
            l_lo += flo.x + flo.y;
            l_hi += fhi.x + fhi.y;
            pf_lo[nt] = plo_u;
            pf_hi[nt] = phi_u;
        }

        // ---- O += P V (fp32 accumulation) ----
        #pragma unroll
        for (int ko2 = 0; ko2 < 4; ko2++) {
            uint32_t pa[4] = { pf_lo[ko2 * 2], pf_hi[ko2 * 2],
                               pf_lo[ko2 * 2 + 1], pf_hi[ko2 * 2 + 1] };
            #pragma unroll
            for (int ntp = 0; ntp < 4; ntp++) {
                uint32_t bf[4];
                ldsm4t(bf, smem_u32(&s.Vs[cur][ko2 * 16 + v_lr][ntp * 16 + v_lc]));
                mma16(oacc[ntp * 2],     pa, bf[0], bf[1]);
                mma16(oacc[ntp * 2 + 1], pa, bf[2], bf[3]);
            }
        }
        cur = cur + 1; if (cur >= 3) cur -= 3;
    }

    l_lo += __shfl_xor_sync(0xffffffffu, l_lo, 1);
    l_lo += __shfl_xor_sync(0xffffffffu, l_lo, 2);
    l_hi += __shfl_xor_sync(0xffffffffu, l_hi, 1);
    l_hi += __shfl_xor_sync(0xffffffffu, l_hi, 2);

    float li_lo = 1.f / l_lo, li_hi = 1.f / l_hi;
    #pragma unroll
    for (int nt = 0; nt < 8; nt++) {
        int c = nt * 8 + 2 * cl;
        size_t base_lo = ((size_t)b * NN + n0 + row_lo) * INNERD + h * DHD + c;
        size_t base_hi = ((size_t)b * NN + n0 + row_lo + 8) * INNERD + h * DHD + c;
        *(__half2*)&g_Oh[base_lo] = __floats2half2_rn(oacc[nt][0] * li_lo, oacc[nt][1] * li_lo);
        *(__half2*)&g_Oh[base_hi] = __floats2half2_rn(oacc[nt][2] * li_hi, oacc[nt][3] * li_hi);
    }
}

// ---------------------------------------------------------------------------
extern "C" void kernel_launch(void* const* d_in, const int* in_sizes, int n_in,
                              void* d_out, int out_size) {
    const float* x            = (const float*)d_in[0];
    const float* ctx          = (const float*)d_in[1];
    const unsigned int* mask  = (const unsigned int*)d_in[2];
    const unsigned int* cmask = (const unsigned int*)d_in[3];
    const float* Wq  = (const float*)d_in[4];
    const float* Wkv = (const float*)d_in[5];
    const float* Wo  = (const float*)d_in[6];
    const float* bo  = (const float*)d_in[7];
    const float* nk  = (const float*)d_in[8];
    const float* nv  = (const float*)d_in[9];
    float* out = (float*)d_out;

    static int inited = 0;
    if (!inited) {
        cudaFuncSetAttribute(attn_kernel, cudaFuncAttributeMaxDynamicSharedMemorySize,
                             (int)sizeof(AttnSmemH));
        inited = 1;
    }

    __half *oh, *woh;
    cudaGetSymbolAddress((void**)&oh,  g_Oh);
    cudaGetSymbolAddress((void**)&woh, g_woh);

    prep_all_kernel<<<NB_ROUND + NB_BIAS + NB_KV, 256>>>(x, ctx, Wq, Wkv, Wo, cmask, nk, nv);

    dim3 gqkv(12, 64);
    gemm_mma_h<<<gqkv, 256>>>(nullptr, nullptr, nullptr, nullptr, 0, 3);

    dim3 ga(NN / QT, HH, BB);                        // (16, 8, 4)
    attn_kernel<<<ga, 256, sizeof(AttnSmemH)>>>(mask);

    dim3 g2(512 / 128, (BB * NN) / 128);             // (4, 64)
    gemm_mma_h<<<g2, 256>>>(oh, woh, bo, out, 512, 2);
}

// round 17
// speedup vs baseline: 1.4360x; 1.0362x over previous
#include <cuda_runtime.h>
#include <cuda_fp16.h>
#include <math.h>
#include <stdint.h>

#define BB 4
#define NN 2048
#define MM 2048
#define HH 8
#define DHD 64
#define INNERD 512
#define MP 2049
#define MPAD 2112          // 33 * 64
#define KT 64
#define QT 128
#define NTILES (MPAD / KT) // 33
#define SCALEQ 0.18033688f // 0.125 * log2(e)

// Scratch (device globals; no allocation allowed)
__device__ __half g_Qh[(size_t)BB*HH*NN*DHD];    // [b,h,n,d]  tanh(q)*0.125*log2e
__device__ __half g_Kh[(size_t)BB*HH*MPAD*DHD];  // [b,h,j,d]  tanh(k), j=0 null, pad 0
__device__ __half g_Vh[(size_t)BB*HH*MPAD*DHD];  // [b,h,j,d]
__device__ __half g_Oh[(size_t)BB*NN*INNERD];    // [b,n,h*d]
__device__ __half g_kmh[BB*MPAD];                // 1 attendable / 0 masked / 0 pad
__device__ __half g_kmh2[BB*MPAD];               // 1 non-pad / 0 pad
__device__ __half g_xh[(size_t)BB*NN*512];
__device__ __half g_ch[(size_t)BB*MM*512];
__device__ __half g_wqh[512*512];
__device__ __half g_wkvh[512*1024];
__device__ __half g_woh[512*512];

__device__ __forceinline__ uint32_t smem_u32(const void* p) {
    return (uint32_t)__cvta_generic_to_shared(p);
}
__device__ __forceinline__ void ldsm4(uint32_t* r, uint32_t a) {
    asm volatile("ldmatrix.sync.aligned.m8n8.x4.shared.b16 {%0,%1,%2,%3}, [%4];"
        : "=r"(r[0]), "=r"(r[1]), "=r"(r[2]), "=r"(r[3]) : "r"(a));
}
__device__ __forceinline__ void ldsm4t(uint32_t* r, uint32_t a) {
    asm volatile("ldmatrix.sync.aligned.m8n8.x4.trans.shared.b16 {%0,%1,%2,%3}, [%4];"
        : "=r"(r[0]), "=r"(r[1]), "=r"(r[2]), "=r"(r[3]) : "r"(a));
}
__device__ __forceinline__ void mma16(float* d, const uint32_t* a, uint32_t b0, uint32_t b1) {
    asm volatile(
        "mma.sync.aligned.m16n8k16.row.col.f32.f16.f16.f32 "
        "{%0,%1,%2,%3}, {%4,%5,%6,%7}, {%8,%9}, {%0,%1,%2,%3};"
        : "+f"(d[0]), "+f"(d[1]), "+f"(d[2]), "+f"(d[3])
        : "r"(a[0]), "r"(a[1]), "r"(a[2]), "r"(a[3]), "r"(b0), "r"(b1));
}
__device__ __forceinline__ void mma16h(uint32_t* d, const uint32_t* a, uint32_t b0, uint32_t b1) {
    asm volatile(
        "mma.sync.aligned.m16n8k16.row.col.f16.f16.f16.f16 "
        "{%0,%1}, {%2,%3,%4,%5}, {%6,%7}, {%0,%1};"
        : "+r"(d[0]), "+r"(d[1])
        : "r"(a[0]), "r"(a[1]), "r"(a[2]), "r"(a[3]), "r"(b0), "r"(b1));
}
__device__ __forceinline__ void cpa16(void* dst, const void* src) {
    uint32_t d = smem_u32(dst);
    asm volatile("cp.async.cg.shared.global [%0], [%1], 16;\n" :: "r"(d), "l"(src));
}
__device__ __forceinline__ uint32_t ex2_f16x2(uint32_t x) {
    uint32_t r;
    asm("ex2.approx.f16x2 %0, %1;" : "=r"(r) : "r"(x));
    return r;
}
#define CP_COMMIT() asm volatile("cp.async.commit_group;\n" ::: "memory")
#define CP_WAIT(n)  asm volatile("cp.async.wait_group %0;\n" :: "n"(n) : "memory")

// ---------------------------------------------------------------------------
// Fused prep (unchanged from R16)
// ---------------------------------------------------------------------------
#define N4_X   (BB*NN*512/4)
#define N4_C   (BB*MM*512/4)
#define N4_WQ  (512*512/4)
#define N4_WKV (512*1024/4)
#define N4_WO  (512*512/4)
#define N4_TOT (N4_X + N4_C + N4_WQ + N4_WKV + N4_WO)
#define NB_ROUND (N4_TOT / 1024)
#define NB_BIAS  ((BB * MPAD + 255) / 256)
#define NB_KV    (BB * HH)

__global__ void prep_all_kernel(const float* __restrict__ x, const float* __restrict__ ctx,
                                const float* __restrict__ wq, const float* __restrict__ wkv,
                                const float* __restrict__ wo,
                                const unsigned int* __restrict__ cmask,
                                const float* __restrict__ null_key,
                                const float* __restrict__ null_value) {
    int blk = blockIdx.x;
    if (blk < NB_ROUND) {
        int i0 = blk * 1024;
        const float* src; __half* dst; int seg0;
        if (i0 < N4_X)                               { src = x;   dst = g_xh;   seg0 = 0; }
        else if (i0 < N4_X + N4_C)                   { src = ctx; dst = g_ch;   seg0 = N4_X; }
        else if (i0 < N4_X + N4_C + N4_WQ)           { src = wq;  dst = g_wqh;  seg0 = N4_X + N4_C; }
        else if (i0 < N4_X + N4_C + N4_WQ + N4_WKV)  { src = wkv; dst = g_wkvh; seg0 = N4_X + N4_C + N4_WQ; }
        else                                         { src = wo;  dst = g_woh;  seg0 = N4_X + N4_C + N4_WQ + N4_WKV; }
        int off0 = i0 - seg0 + threadIdx.x;
        float4 v[4];
        #pragma unroll
        for (int j = 0; j < 4; j++)
            v[j] = ((const float4*)src)[off0 + j * 256];
        #pragma unroll
        for (int j = 0; j < 4; j++) {
            __half2 a = __floats2half2_rn(v[j].x, v[j].y);
            __half2 b = __floats2half2_rn(v[j].z, v[j].w);
            uint2 o; o.x = *(uint32_t*)&a; o.y = *(uint32_t*)&b;
            ((uint2*)dst)[off0 + j * 256] = o;
        }
    } else if (blk < NB_ROUND + NB_BIAS) {
        int t = (blk - NB_ROUND) * 256 + threadIdx.x;
        if (t >= BB * MPAD) return;
        int b = t / MPAD, j = t % MPAD;
        float m, m2;
        if (j == 0)        { m = 1.f; m2 = 1.f; }
        else if (j <= MM)  { m = (cmask[b * MM + (j - 1)] != 0u) ? 1.f : 0.f; m2 = 1.f; }
        else               { m = 0.f; m2 = 0.f; }
        g_kmh[t]  = __float2half_rn(m);
        g_kmh2[t] = __float2half_rn(m2);
    } else {
        int bh = blk - NB_ROUND - NB_BIAS;
        __half* Kb = g_Kh + (size_t)bh * MPAD * DHD;
        __half* Vb = g_Vh + (size_t)bh * MPAD * DHD;
        int t = threadIdx.x;
        if (t < DHD) {
            Kb[t] = __float2half_rn(tanhf(null_key[t]));
            Vb[t] = __float2half_rn(null_value[t]);
        }
        for (int idx = t; idx < DHD * (MPAD - MP); idx += 256) {
            int d = idx & 63, jr = idx >> 6;
            Kb[(size_t)(MP + jr) * DHD + d] = __float2half_rn(0.f);
            Vb[(size_t)(MP + jr) * DHD + d] = __float2half_rn(0.f);
        }
    }
}

// ---------------------------------------------------------------------------
// fp16 mma GEMM (unchanged from R16): k-chunk 32, 3-stage ring, 2 CTA/SM
// ---------------------------------------------------------------------------
__global__ __launch_bounds__(256, 2) void gemm_mma_h(
    const __half* __restrict__ A, const __half* __restrict__ W,
    const float* __restrict__ bias, float* __restrict__ out,
    int Ncols, int mode)
{
    __shared__ __align__(16) __half As[3][128][40];
    __shared__ __align__(16) __half Bs[3][32][136];

    int t = threadIdx.x, lane = t & 31, w = t >> 5;
    int wm = w >> 2, wn = w & 3;
    int g = lane >> 2, cl = lane & 3;
    int row0 = blockIdx.y * 128;
    int col0;
    if (mode == 3) {
        if (blockIdx.x < 4) { A = g_xh; W = g_wqh;  Ncols = 512;  mode = 0; col0 = blockIdx.x * 128; }
        else                { A = g_ch; W = g_wkvh; Ncols = 1024; mode = 1; col0 = (blockIdx.x - 4) * 128; }
    } else {
        col0 = blockIdx.x * 128;
    }

    int ar0 = t >> 2, ac = (t & 3) * 8;
    int br0 = t >> 4, bc = (t & 15) * 8;

    float acc[4][4][4] = {};

    #pragma unroll
    for (int st = 0; st < 2; st++) {
        int k0 = st * 32;
        cpa16(&As[st][ar0][ac],      A + (size_t)(row0 + ar0) * 512 + k0 + ac);
        cpa16(&As[st][ar0 + 64][ac], A + (size_t)(row0 + ar0 + 64) * 512 + k0 + ac);
        cpa16(&Bs[st][br0][bc],      W + (size_t)(k0 + br0) * Ncols + col0 + bc);
        cpa16(&Bs[st][br0 + 16][bc], W + (size_t)(k0 + br0 + 16) * Ncols + col0 + bc);
        CP_COMMIT();
    }

    int a_lr = lane & 15, a_lc = (lane >> 4) * 8;
    int b_lr = (lane & 7) + 8 * ((lane >> 3) & 1), b_lc = 8 * (lane >> 4);

    int cur = 0;
    for (int kt = 0; kt < 16; kt++) {
        if (kt == 15) { CP_WAIT(0); } else { CP_WAIT(1); }
        __syncthreads();

        if (kt < 14) {
            int nb = cur + 2; if (nb >= 3) nb -= 3;
            int k0 = (kt + 2) * 32;
            cpa16(&As[nb][ar0][ac],      A + (size_t)(row0 + ar0) * 512 + k0 + ac);
            cpa16(&As[nb][ar0 + 64][ac], A + (size_t)(row0 + ar0 + 64) * 512 + k0 + ac);
            cpa16(&Bs[nb][br0][bc],      W + (size_t)(k0 + br0) * Ncols + col0 + bc);
            cpa16(&Bs[nb][br0 + 16][bc], W + (size_t)(k0 + br0 + 16) * Ncols + col0 + bc);
            CP_COMMIT();
        }

        #pragma unroll
        for (int kc = 0; kc < 2; kc++) {
            uint32_t af[4][4];
            #pragma unroll
            for (int mi = 0; mi < 4; mi++)
                ldsm4(af[mi], smem_u32(&As[cur][wm * 64 + mi * 16 + a_lr][kc * 16 + a_lc]));
            #pragma unroll
            for (int np = 0; np < 2; np++) {
                uint32_t bf[4];
                ldsm4t(bf, smem_u32(&Bs[cur][kc * 16 + b_lr][wn * 32 + np * 16 + b_lc]));
                #pragma unroll
                for (int mi = 0; mi < 4; mi++) {
                    mma16(acc[mi][np * 2],     af[mi], bf[0], bf[1]);
                    mma16(acc[mi][np * 2 + 1], af[mi], bf[2], bf[3]);
                }
            }
        }
        cur = cur + 1; if (cur >= 3) cur -= 3;
    }

    int bidx = row0 >> 11;
    #pragma unroll
    for (int mi = 0; mi < 4; mi++) {
        int r0 = row0 + wm * 64 + mi * 16 + g;
        int n0r = r0 & 2047;
        #pragma unroll
        for (int ni = 0; ni < 4; ni++) {
            int c = col0 + wn * 32 + ni * 8 + 2 * cl;
            float v0 = acc[mi][ni][0], v1 = acc[mi][ni][1];
            float v2 = acc[mi][ni][2], v3 = acc[mi][ni][3];
            if (mode == 0) {
                int hh = c >> 6, d = c & 63;
                *(__half2*)&g_Qh[(((size_t)bidx * HH + hh) * NN + n0r) * DHD + d] =
                    __floats2half2_rn(tanhf(v0) * SCALEQ, tanhf(v1) * SCALEQ);
                *(__half2*)&g_Qh[(((size_t)bidx * HH + hh) * NN + n0r + 8) * DHD + d] =
                    __floats2half2_rn(tanhf(v2) * SCALEQ, tanhf(v3) * SCALEQ);
            } else if (mode == 1) {
                if (c < INNERD) {
                    int hh = c >> 6, d = c & 63;
                    *(__half2*)&g_Kh[(((size_t)bidx * HH + hh) * MPAD + n0r + 1) * DHD + d] =
                        __floats2half2_rn(tanhf(v0), tanhf(v1));
                    *(__half2*)&g_Kh[(((size_t)bidx * HH + hh) * MPAD + n0r + 9) * DHD + d] =
                        __floats2half2_rn(tanhf(v2), tanhf(v3));
                } else {
                    int c2 = c - INNERD;
                    int hh = c2 >> 6, d = c2 & 63;
                    *(__half2*)&g_Vh[(((size_t)bidx * HH + hh) * MPAD + n0r + 1) * DHD + d] =
                        __floats2half2_rn(v0, v1);
                    *(__half2*)&g_Vh[(((size_t)bidx * HH + hh) * MPAD + n0r + 9) * DHD + d] =
                        __floats2half2_rn(v2, v3);
                }
            } else {
                float b0v = bias[c], b1v = bias[c + 1];
                *(float2*)&out[(size_t)r0 * 512 + c]       = make_float2(v0 + b0v, v1 + b1v);
                *(float2*)&out[(size_t)(r0 + 8) * 512 + c] = make_float2(v2 + b0v, v3 + b1v);
            }
        }
    }
}

// ---------------------------------------------------------------------------
// Flash attention: FAT WARP TILE — 4 warps x 32 q-rows (2 A-frag groups per
// warp; each K/V B-fragment feeds 2 mma). fp16 S-acc, log2-domain ex2.f16x2
// softmax, register P, fp32 PV, 3-stage cp.async ring. 128 thr, 2 CTA/SM.
// ---------------------------------------------------------------------------
struct __align__(16) AttnSmemH {
    __half Qs[128][72];
    __half Kt[3][64][72];
    __half Vs[3][64][72];
    __half kmh[3][64];
    __half kmh2[3][64];
};

__device__ __forceinline__ void cp_kv_tile(AttnSmemH& s, int buf, const __half* Kb,
                                           const __half* Vb, int j0, int t) {
    #pragma unroll
    for (int i = 0; i < 4; i++) {
        int e = t + i * 128;
        int r = e >> 3, c8 = (e & 7) * 8;
        cpa16(&s.Kt[buf][r][c8], Kb + (size_t)(j0 + r) * DHD + c8);
        cpa16(&s.Vs[buf][r][c8], Vb + (size_t)(j0 + r) * DHD + c8);
    }
}

__global__ __launch_bounds__(128, 2) void attn_kernel(const unsigned int* __restrict__ qmask) {
    extern __shared__ char smem_raw[];
    AttnSmemH& s = *reinterpret_cast<AttnSmemH*>(smem_raw);

    int t = threadIdx.x, lane = t & 31, w = t >> 5;   // 4 warps
    int n0 = blockIdx.x * QT;
    int h = blockIdx.y, b = blockIdx.z;
    int bh = b * HH + h;

    const __half* Qb = g_Qh + (size_t)bh * NN * DHD;
    const __half* Kb = g_Kh + (size_t)bh * MPAD * DHD;
    const __half* Vb = g_Vh + (size_t)bh * MPAD * DHD;
    const __half* km_base  = g_kmh  + b * MPAD;
    const __half* km2_base = g_kmh2 + b * MPAD;

    #pragma unroll
    for (int i = 0; i < 8; i++) {
        int e = t + i * 128;
        int q = e >> 3, c8 = (e & 7) * 8;
        *(uint4*)&s.Qs[q][c8] = *(const uint4*)&Qb[(size_t)(n0 + q) * DHD + c8];
    }
    #pragma unroll
    for (int st = 0; st < 2; st++) {
        cp_kv_tile(s, st, Kb, Vb, st * KT, t);
        CP_COMMIT();
        if (t < 32) {
            ((uint32_t*)s.kmh[st])[t]  = ((const uint32_t*)(km_base  + st * KT))[t];
            ((uint32_t*)s.kmh2[st])[t] = ((const uint32_t*)(km2_base + st * KT))[t];
        }
    }
    __syncthreads();

    int g = lane >> 2, cl = lane & 3;
    int a_lr = lane & 15, a_lc = (lane >> 4) * 8;

    // 2 row-groups of 16 per warp: rows w*32 + rg*16 + {g, g+8}
    uint32_t aq[2][4][4];
    #pragma unroll
    for (int rg = 0; rg < 2; rg++)
        #pragma unroll
        for (int ko = 0; ko < 4; ko++)
            ldsm4(aq[rg][ko], smem_u32(&s.Qs[w * 32 + rg * 16 + a_lr][ko * 16 + a_lc]));

    int qm[2][2];
    #pragma unroll
    for (int rg = 0; rg < 2; rg++) {
        qm[rg][0] = (qmask[b * NN + n0 + w * 32 + rg * 16 + g]     != 0u) ? 1 : 0;
        qm[rg][1] = (qmask[b * NN + n0 + w * 32 + rg * 16 + g + 8] != 0u) ? 1 : 0;
    }

    float l[2][2] = {};
    float oacc[2][8][4] = {};
    int cur = 0;

    int k_lr = (lane & 7) + 8 * (lane >> 4);
    int k_lc = 8 * ((lane >> 3) & 1);
    int v_lr = (lane & 7) + 8 * ((lane >> 3) & 1);
    int v_lc = 8 * (lane >> 4);

    for (int kt = 0; kt < NTILES; kt++) {
        if (kt == NTILES - 1) { CP_WAIT(0); } else { CP_WAIT(1); }
        __syncthreads();

        if (kt < NTILES - 2) {
            int nb = cur + 2; if (nb >= 3) nb -= 3;
            int j1 = (kt + 2) * KT;
            cp_kv_tile(s, nb, Kb, Vb, j1, t);
            CP_COMMIT();
            if (t < 32) {
                ((uint32_t*)s.kmh[nb])[t]  = ((const uint32_t*)(km_base  + j1))[t];
                ((uint32_t*)s.kmh2[nb])[t] = ((const uint32_t*)(km2_base + j1))[t];
            }
        }

        // ---- S' = Q K^T (log2 domain), fp16 acc, both row-groups per B-frag
        uint32_t sacc[2][8][2] = {};
        #pragma unroll
        for (int ko = 0; ko < 4; ko++) {
            #pragma unroll
            for (int ntp = 0; ntp < 4; ntp++) {
                uint32_t bf[4];
                ldsm4(bf, smem_u32(&s.Kt[cur][ntp * 16 + k_lr][ko * 16 + k_lc]));
                #pragma unroll
                for (int rg = 0; rg < 2; rg++) {
                    mma16h(sacc[rg][ntp * 2],     aq[rg][ko], bf[0], bf[1]);
                    mma16h(sacc[rg][ntp * 2 + 1], aq[rg][ko], bf[2], bf[3]);
                }
            }
        }

        // ---- softmax: p = ex2(s') * mask (packed f16x2) ----
        uint32_t pf[2][2][8];   // [rg][lo/hi][nt]
        #pragma unroll
        for (int rg = 0; rg < 2; rg++) {
            #pragma unroll
            for (int nt = 0; nt < 8; nt++) {
                uint32_t m  = ((const uint32_t*)s.kmh[cur])[nt * 4 + cl];
                uint32_t m2 = ((const uint32_t*)s.kmh2[cur])[nt * 4 + cl];
                uint32_t elo = ex2_f16x2(sacc[rg][nt][0]);
                uint32_t ehi = ex2_f16x2(sacc[rg][nt][1]);
                __half2 plo = __hmul2(*(__half2*)&elo, *(__half2*)&m);
                __half2 phi = __hmul2(*(__half2*)&ehi, *(__half2*)&m);
                uint32_t plo_u = qm[rg][0] ? *(uint32_t*)&plo : m2;
                uint32_t phi_u = qm[rg][1] ? *(uint32_t*)&phi : m2;
                float2 flo = __half22float2(*(__half2*)&plo_u);
                float2 fhi = __half22float2(*(__half2*)&phi_u);
                l[rg][0] += flo.x + flo.y;
                l[rg][1] += fhi.x + fhi.y;
                pf[rg][0][nt] = plo_u;
                pf[rg][1][nt] = phi_u;
            }
        }

        // ---- O += P V (fp32 acc), both row-groups per V B-frag ----
        #pragma unroll
        for (int ko2 = 0; ko2 < 4; ko2++) {
            #pragma unroll
            for (int ntp = 0; ntp < 4; ntp++) {
                uint32_t bf[4];
                ldsm4t(bf, smem_u32(&s.Vs[cur][ko2 * 16 + v_lr][ntp * 16 + v_lc]));
                #pragma unroll
                for (int rg = 0; rg < 2; rg++) {
                    uint32_t pa[4] = { pf[rg][0][ko2 * 2], pf[rg][1][ko2 * 2],
                                       pf[rg][0][ko2 * 2 + 1], pf[rg][1][ko2 * 2 + 1] };
                    mma16(oacc[rg][ntp * 2],     pa, bf[0], bf[1]);
                    mma16(oacc[rg][ntp * 2 + 1], pa, bf[2], bf[3]);
                }
            }
        }
        cur = cur + 1; if (cur >= 3) cur -= 3;
    }

    #pragma unroll
    for (int rg = 0; rg < 2; rg++) {
        l[rg][0] += __shfl_xor_sync(0xffffffffu, l[rg][0], 1);
        l[rg][0] += __shfl_xor_sync(0xffffffffu, l[rg][0], 2);
        l[rg][1] += __shfl_xor_sync(0xffffffffu, l[rg][1], 1);
        l[rg][1] += __shfl_xor_sync(0xffffffffu, l[rg][1], 2);
        float li_lo = 1.f / l[rg][0], li_hi = 1.f / l[rg][1];
        int row_lo = w * 32 + rg * 16 + g;
        #pragma unroll
        for (int nt = 0; nt < 8; nt++) {
            int c = nt * 8 + 2 * cl;
            size_t base_lo = ((size_t)b * NN + n0 + row_lo) * INNERD + h * DHD + c;
            size_t base_hi = ((size_t)b * NN + n0 + row_lo + 8) * INNERD + h * DHD + c;
            *(__half2*)&g_Oh[base_lo] =
                __floats2half2_rn(oacc[rg][nt][0] * li_lo, oacc[rg][nt][1] * li_lo);
            *(__half2*)&g_Oh[base_hi] =
                __floats2half2_rn(oacc[rg][nt][2] * li_hi, oacc[rg][nt][3] * li_hi);
        }
    }
}

// ---------------------------------------------------------------------------
extern "C" void kernel_launch(void* const* d_in, const int* in_sizes, int n_in,
                              void* d_out, int out_size) {
    const float* x            = (const float*)d_in[0];
    const float* ctx          = (const float*)d_in[1];
    const unsigned int* mask  = (const unsigned int*)d_in[2];
    const unsigned int* cmask = (const unsigned int*)d_in[3];
    const float* Wq  = (const float*)d_in[4];
    const float* Wkv = (const float*)d_in[5];
    const float* Wo  = (const float*)d_in[6];
    const float* bo  = (const float*)d_in[7];
    const float* nk  = (const float*)d_in[8];
    const float* nv  = (const float*)d_in[9];
    float* out = (float*)d_out;

    static int inited = 0;
    if (!inited) {
        cudaFuncSetAttribute(attn_kernel, cudaFuncAttributeMaxDynamicSharedMemorySize,
                             (int)sizeof(AttnSmemH));
        inited = 1;
    }

    __half *oh, *woh;
    cudaGetSymbolAddress((void**)&oh,  g_Oh);
    cudaGetSymbolAddress((void**)&woh, g_woh);

    prep_all_kernel<<<NB_ROUND + NB_BIAS + NB_KV, 256>>>(x, ctx, Wq, Wkv, Wo, cmask, nk, nv);

    dim3 gqkv(12, 64);
    gemm_mma_h<<<gqkv, 256>>>(nullptr, nullptr, nullptr, nullptr, 0, 3);

    dim3 ga(NN / QT, HH, BB);                        // (16, 8, 4)
    attn_kernel<<<ga, 128, sizeof(AttnSmemH)>>>(mask);

    dim3 g2(512 / 128, (BB * NN) / 128);             // (4, 64)
    gemm_mma_h<<<g2, 256>>>(oh, woh, bo, out, 512, 2);
}